// round 1
// baseline (speedup 1.0000x reference)
#include <cuda_runtime.h>

#define B_  8
#define S_  1024
#define NX_ 1024
#define H_  16
#define D_  64

// Scratch (allocation-free rule: __device__ globals)
__device__ float g_qkv[B_ * S_ * 3 * NX_];   // [B,S,3*NX]
__device__ float g_attn[B_ * S_ * NX_];      // [B,S,NX]

// ---------------------------------------------------------------------------
// SGEMM with bias: C[M,N] = A[M,K] @ B[K,N] + bias[N]
// BM=BN=128, BK=8, 256 threads, 8x8 per thread. M%128==0, N%128==0, K%8==0.
// ---------------------------------------------------------------------------
__global__ void __launch_bounds__(256, 2) sgemm128(
    const float* __restrict__ A, const float* __restrict__ Bm,
    const float* __restrict__ bias, float* __restrict__ C,
    int M, int N, int K)
{
    constexpr int BM = 128, BN = 128, BK = 8, TM = 8, TN = 8;
    __shared__ float As[BK][BM];
    __shared__ float Bs[BK][BN];

    const int tid = threadIdx.x;
    const int bm  = blockIdx.y * BM;
    const int bn  = blockIdx.x * BN;
    const int tx  = tid & 15;   // 16 col groups
    const int ty  = tid >> 4;   // 16 row groups

    float acc[TM][TN];
#pragma unroll
    for (int i = 0; i < TM; i++)
#pragma unroll
        for (int j = 0; j < TN; j++) acc[i][j] = 0.f;

    const int aRow = tid >> 1;            // 0..127
    const int aCol = (tid & 1) * 4;       // 0 or 4
    const int bRow = tid >> 5;            // 0..7
    const int bCol = (tid & 31) * 4;      // 0..124

    const float* Aptr = A + (long)(bm + aRow) * K + aCol;
    const float* Bptr = Bm + (long)bRow * N + bn + bCol;

    for (int k0 = 0; k0 < K; k0 += BK) {
        float4 a4 = *(const float4*)(Aptr + k0);
        As[aCol + 0][aRow] = a4.x;
        As[aCol + 1][aRow] = a4.y;
        As[aCol + 2][aRow] = a4.z;
        As[aCol + 3][aRow] = a4.w;
        float4 b4 = *(const float4*)(Bptr + (long)k0 * N);
        *(float4*)&Bs[bRow][bCol] = b4;
        __syncthreads();

#pragma unroll
        for (int k = 0; k < BK; k++) {
            float4 ra0 = *(const float4*)&As[k][ty * TM];
            float4 ra1 = *(const float4*)&As[k][ty * TM + 4];
            float4 rb0 = *(const float4*)&Bs[k][tx * TN];
            float4 rb1 = *(const float4*)&Bs[k][tx * TN + 4];
            float ra[TM] = {ra0.x, ra0.y, ra0.z, ra0.w, ra1.x, ra1.y, ra1.z, ra1.w};
            float rb[TN] = {rb0.x, rb0.y, rb0.z, rb0.w, rb1.x, rb1.y, rb1.z, rb1.w};
#pragma unroll
            for (int i = 0; i < TM; i++)
#pragma unroll
                for (int j = 0; j < TN; j++)
                    acc[i][j] += ra[i] * rb[j];
        }
        __syncthreads();
    }

#pragma unroll
    for (int i = 0; i < TM; i++) {
        const long row = bm + ty * TM + i;
#pragma unroll
        for (int j = 0; j < TN; j += 4) {
            const int col = bn + tx * TN + j;
            float4 o;
            o.x = acc[i][j + 0] + bias[col + 0];
            o.y = acc[i][j + 1] + bias[col + 1];
            o.z = acc[i][j + 2] + bias[col + 2];
            o.w = acc[i][j + 3] + bias[col + 3];
            *(float4*)&C[row * N + col] = o;
        }
    }
}

// ---------------------------------------------------------------------------
// Causal flash-attention, fp32. One CTA per (b, h, 64-row q tile).
// 256 threads = 16x16; each thread owns a 4x4 (rows x out-dims) patch.
// ---------------------------------------------------------------------------
#define ATTN_SMEM_BYTES (4 * 64 * 65 * 4)

__global__ void __launch_bounds__(256) attn_kernel(
    const float* __restrict__ qkv, float* __restrict__ out)
{
    extern __shared__ float sm[];
    float (*Qs)[65] = (float (*)[65])sm;                 // [d][r], pre-scaled
    float (*Ks)[65] = (float (*)[65])(sm + 64 * 65);     // [d][c]
    float (*Vs)[65] = (float (*)[65])(sm + 2 * 64 * 65); // [k][c]
    float (*Ps)[65] = (float (*)[65])(sm + 3 * 64 * 65); // [r][k]

    const int tid = threadIdx.x;
    const int qt  = blockIdx.x;           // q tile (0..15)
    const int h   = blockIdx.y;
    const int b   = blockIdx.z;
    const int q0  = qt * 64;
    const int tx  = tid & 15;
    const int ty  = tid >> 4;

    const float scale = 0.125f;           // 1/sqrt(64)
    const long base = (long)b * S_ * (3 * NX_);

    // Load Q tile, transposed [d][r], scaled
#pragma unroll
    for (int i = 0; i < 16; i++) {
        int idx = tid + i * 256;
        int r = idx >> 6, d = idx & 63;
        Qs[d][r] = qkv[base + (long)(q0 + r) * (3 * NX_) + h * D_ + d] * scale;
    }

    float m[4], l[4], acc[4][4];
#pragma unroll
    for (int i = 0; i < 4; i++) {
        m[i] = -1e30f; l[i] = 0.f;
#pragma unroll
        for (int j = 0; j < 4; j++) acc[i][j] = 0.f;
    }

    for (int kt = 0; kt <= qt; kt++) {
        __syncthreads();  // protect Ks/Vs reuse from previous PV (also orders Qs on iter 0)
#pragma unroll
        for (int i = 0; i < 16; i++) {
            int idx = tid + i * 256;
            int r = idx >> 6, d = idx & 63;
            long krow = base + (long)(kt * 64 + r) * (3 * NX_);
            Ks[d][r] = qkv[krow + NX_ + h * D_ + d];
            Vs[r][d] = qkv[krow + 2 * NX_ + h * D_ + d];
        }
        __syncthreads();

        // S = (Q*scale) @ K^T  -> 4x4 per thread
        float s[4][4];
#pragma unroll
        for (int i = 0; i < 4; i++)
#pragma unroll
            for (int j = 0; j < 4; j++) s[i][j] = 0.f;

#pragma unroll 8
        for (int d = 0; d < 64; d++) {
            float ra[4], rb[4];
#pragma unroll
            for (int i = 0; i < 4; i++) ra[i] = Qs[d][ty * 4 + i];
#pragma unroll
            for (int j = 0; j < 4; j++) rb[j] = Ks[d][tx * 4 + j];
#pragma unroll
            for (int i = 0; i < 4; i++)
#pragma unroll
                for (int j = 0; j < 4; j++)
                    s[i][j] += ra[i] * rb[j];
        }

        // Causal mask on diagonal tile (matches reference: masked score = -1e9)
        if (kt == qt) {
#pragma unroll
            for (int i = 0; i < 4; i++)
#pragma unroll
                for (int j = 0; j < 4; j++)
                    if (tx * 4 + j > ty * 4 + i) s[i][j] = -1e9f;
        }

        // Online softmax (row group = 16 lanes sharing ty)
#pragma unroll
        for (int i = 0; i < 4; i++) {
            float mx = fmaxf(fmaxf(s[i][0], s[i][1]), fmaxf(s[i][2], s[i][3]));
#pragma unroll
            for (int off = 8; off > 0; off >>= 1)
                mx = fmaxf(mx, __shfl_xor_sync(0xffffffffu, mx, off));
            float mnew = fmaxf(m[i], mx);
            float alpha = __expf(m[i] - mnew);
            m[i] = mnew;
            float rs = 0.f;
#pragma unroll
            for (int j = 0; j < 4; j++) {
                s[i][j] = __expf(s[i][j] - mnew);
                rs += s[i][j];
            }
#pragma unroll
            for (int off = 8; off > 0; off >>= 1)
                rs += __shfl_xor_sync(0xffffffffu, rs, off);
            l[i] = l[i] * alpha + rs;
#pragma unroll
            for (int j = 0; j < 4; j++) {
                acc[i][j] *= alpha;
                Ps[ty * 4 + i][tx * 4 + j] = s[i][j];
            }
        }
        __syncthreads();

        // O += P @ V
#pragma unroll 8
        for (int k = 0; k < 64; k++) {
            float rv[4];
#pragma unroll
            for (int j = 0; j < 4; j++) rv[j] = Vs[k][tx * 4 + j];
#pragma unroll
            for (int i = 0; i < 4; i++) {
                float p = Ps[ty * 4 + i][k];
#pragma unroll
                for (int j = 0; j < 4; j++)
                    acc[i][j] += p * rv[j];
            }
        }
    }

    // Epilogue: normalize, write [B,S,NX] with head h at cols h*64..h*64+63
#pragma unroll
    for (int i = 0; i < 4; i++) {
        float inv = 1.f / l[i];
        float4 o;
        o.x = acc[i][0] * inv;
        o.y = acc[i][1] * inv;
        o.z = acc[i][2] * inv;
        o.w = acc[i][3] * inv;
        long row = (long)b * S_ + q0 + ty * 4 + i;
        *(float4*)&out[row * NX_ + h * D_ + tx * 4] = o;
    }
}

// ---------------------------------------------------------------------------
extern "C" void kernel_launch(void* const* d_in, const int* in_sizes, int n_in,
                              void* d_out, int out_size)
{
    const float* x      = (const float*)d_in[0];
    const float* w_attn = (const float*)d_in[1];
    const float* b_attn = (const float*)d_in[2];
    const float* w_proj = (const float*)d_in[3];
    const float* b_proj = (const float*)d_in[4];
    float* out = (float*)d_out;

    float *qkv, *attn;
    cudaGetSymbolAddress((void**)&qkv, g_qkv);
    cudaGetSymbolAddress((void**)&attn, g_attn);

    // 1) QKV: [8192,1024] @ [1024,3072] + b_attn
    {
        dim3 grid(3 * NX_ / 128, (B_ * S_) / 128);
        sgemm128<<<grid, 256>>>(x, w_attn, b_attn, qkv, B_ * S_, 3 * NX_, NX_);
    }
    // 2) Causal attention
    {
        cudaFuncSetAttribute(attn_kernel,
                             cudaFuncAttributeMaxDynamicSharedMemorySize,
                             ATTN_SMEM_BYTES);
        dim3 grid(S_ / 64, H_, B_);
        attn_kernel<<<grid, 256, ATTN_SMEM_BYTES>>>(qkv, attn);
    }
    // 3) Projection: [8192,1024] @ [1024,1024] + b_proj
    {
        dim3 grid(NX_ / 128, (B_ * S_) / 128);
        sgemm128<<<grid, 256>>>(attn, w_proj, b_proj, out, B_ * S_, NX_, NX_);
    }
}

// round 3
// speedup vs baseline: 1.3929x; 1.3929x over previous
#include <cuda_runtime.h>
#include <cuda_bf16.h>
#include <cstdint>

#define B_  8
#define S_  1024
#define NX_ 1024
#define H_  16
#define D_  64

// ---------------- scratch (__device__ globals; no allocation) ----------------
__device__ float g_qkv[B_ * S_ * 3 * NX_];           // [B,S,3*NX] fp32
__device__ float g_attn[B_ * S_ * NX_];              // [B,S,NX]   fp32
__device__ __nv_bfloat16 g_xhi[B_ * S_ * NX_];
__device__ __nv_bfloat16 g_xlo[B_ * S_ * NX_];
__device__ __nv_bfloat16 g_ahi[B_ * S_ * NX_];
__device__ __nv_bfloat16 g_alo[B_ * S_ * NX_];
__device__ __nv_bfloat16 g_wqkv_hi[3 * NX_ * NX_];   // [N=3072, K=1024] (transposed)
__device__ __nv_bfloat16 g_wqkv_lo[3 * NX_ * NX_];
__device__ __nv_bfloat16 g_wproj_hi[NX_ * NX_];      // [N=1024, K=1024]
__device__ __nv_bfloat16 g_wproj_lo[NX_ * NX_];

// ---------------- PTX helpers (baseline ISA only: sm_80-era ops) -------------
__device__ __forceinline__ uint32_t smem_to_u32(const void* p) {
    uint32_t a;
    asm("{ .reg .u64 t; cvta.to.shared.u64 t, %1; cvt.u32.u64 %0, t; }"
        : "=r"(a) : "l"(p));
    return a;
}
__device__ __forceinline__ void cp_async16(uint32_t dst, const void* src) {
    asm volatile("cp.async.cg.shared.global [%0], [%1], 16;"
                 :: "r"(dst), "l"(src) : "memory");
}
#define CP_COMMIT() asm volatile("cp.async.commit_group;" ::: "memory")
#define CP_WAIT(n)  asm volatile("cp.async.wait_group %0;" :: "n"(n) : "memory")

__device__ __forceinline__ void ldsm_x4(uint32_t& r0, uint32_t& r1,
                                        uint32_t& r2, uint32_t& r3, uint32_t addr) {
    asm volatile("ldmatrix.sync.aligned.m8n8.x4.shared.b16 {%0,%1,%2,%3}, [%4];"
                 : "=r"(r0), "=r"(r1), "=r"(r2), "=r"(r3) : "r"(addr));
}
__device__ __forceinline__ void ldsm_x2(uint32_t& r0, uint32_t& r1, uint32_t addr) {
    asm volatile("ldmatrix.sync.aligned.m8n8.x2.shared.b16 {%0,%1}, [%2];"
                 : "=r"(r0), "=r"(r1) : "r"(addr));
}
__device__ __forceinline__ void mma16816(float* c, const uint32_t* a, const uint32_t* b) {
    asm volatile("mma.sync.aligned.m16n8k16.row.col.f32.bf16.bf16.f32 "
                 "{%0,%1,%2,%3}, {%4,%5,%6,%7}, {%8,%9}, {%0,%1,%2,%3};"
                 : "+f"(c[0]), "+f"(c[1]), "+f"(c[2]), "+f"(c[3])
                 : "r"(a[0]), "r"(a[1]), "r"(a[2]), "r"(a[3]),
                   "r"(b[0]), "r"(b[1]));
}

// ---------------------------------------------------------------------------
// split: fp32 -> (hi, lo) bf16, same layout. n4 = n/4.
// ---------------------------------------------------------------------------
__global__ void split_kernel(const float* __restrict__ in,
                             __nv_bfloat16* __restrict__ hi,
                             __nv_bfloat16* __restrict__ lo, int n4)
{
    int i = blockIdx.x * blockDim.x + threadIdx.x;
    if (i >= n4) return;
    float4 v = ((const float4*)in)[i];
    __nv_bfloat16 h0 = __float2bfloat16(v.x);
    __nv_bfloat16 h1 = __float2bfloat16(v.y);
    __nv_bfloat16 h2 = __float2bfloat16(v.z);
    __nv_bfloat16 h3 = __float2bfloat16(v.w);
    __nv_bfloat16 l0 = __float2bfloat16(v.x - __bfloat162float(h0));
    __nv_bfloat16 l1 = __float2bfloat16(v.y - __bfloat162float(h1));
    __nv_bfloat16 l2 = __float2bfloat16(v.z - __bfloat162float(h2));
    __nv_bfloat16 l3 = __float2bfloat16(v.w - __bfloat162float(h3));
    ((__nv_bfloat162*)hi)[2 * i]     = __nv_bfloat162(h0, h1);
    ((__nv_bfloat162*)hi)[2 * i + 1] = __nv_bfloat162(h2, h3);
    ((__nv_bfloat162*)lo)[2 * i]     = __nv_bfloat162(l0, l1);
    ((__nv_bfloat162*)lo)[2 * i + 1] = __nv_bfloat162(l2, l3);
}

// ---------------------------------------------------------------------------
// transpose + split: W[K,N] fp32 -> T_hi/T_lo [N,K] bf16
// ---------------------------------------------------------------------------
__global__ void tsplit_kernel(const float* __restrict__ W,
                              __nv_bfloat16* __restrict__ Thi,
                              __nv_bfloat16* __restrict__ Tlo, int K, int N)
{
    __shared__ float t[32][33];
    int n0 = blockIdx.x * 32, k0 = blockIdx.y * 32;
    int tx = threadIdx.x, ty = threadIdx.y;  // 32 x 8
#pragma unroll
    for (int i = 0; i < 4; i++)
        t[ty + i * 8][tx] = W[(long)(k0 + ty + i * 8) * N + n0 + tx];
    __syncthreads();
#pragma unroll
    for (int i = 0; i < 4; i++) {
        float v = t[tx][ty + i * 8];
        __nv_bfloat16 h = __float2bfloat16(v);
        __nv_bfloat16 l = __float2bfloat16(v - __bfloat162float(h));
        long o = (long)(n0 + ty + i * 8) * K + k0 + tx;
        Thi[o] = h;
        Tlo[o] = l;
    }
}

// ---------------------------------------------------------------------------
// bf16-split GEMM on mma.sync (HMMA):
//   C[M,N] = Ahi/lo[M,K] x (Bhi/lo[N,K])^T + bias[N]
// 128x128x32 tiles, 256 threads (8 warps: 2 along M x 4 along N, 64x32 each),
// double-buffered cp.async.
// ---------------------------------------------------------------------------
#define ROWB    80                       // 32 bf16 (64B) + 16B pad, 16B-aligned
#define TILE_B  (128 * ROWB)             // 10240 B
#define STAGE_B (4 * TILE_B)             // Ahi Alo Bhi Blo = 40960 B
#define GEMM_SMEM_DYN (2 * STAGE_B)      // 81920 B

__global__ void __launch_bounds__(256, 1) gemm_mma(
    const __nv_bfloat16* __restrict__ Ahi, const __nv_bfloat16* __restrict__ Alo,
    const __nv_bfloat16* __restrict__ Bhi, const __nv_bfloat16* __restrict__ Blo,
    const float* __restrict__ bias, float* __restrict__ C,
    int M, int N, int K)
{
    extern __shared__ __align__(128) char smem[];
    const uint32_t sbase = smem_to_u32(smem);

    const int tid  = threadIdx.x;
    const int lane = tid & 31;
    const int wid  = tid >> 5;
    const int wm   = wid & 1;        // 2 warps along M
    const int wn   = wid >> 1;       // 4 warps along N
    const int bm   = blockIdx.y * 128;
    const int bn   = blockIdx.x * 128;

    float acc[4][4][4];
#pragma unroll
    for (int mi = 0; mi < 4; mi++)
#pragma unroll
        for (int ni = 0; ni < 4; ni++)
#pragma unroll
            for (int r = 0; r < 4; r++) acc[mi][ni][r] = 0.f;

    const int row = tid & 127;       // smem tile row this thread fills
    const int ch  = tid >> 7;        // chunk pair base (0 or 1); +2 on j=1

    const __nv_bfloat16* gA[2] = { Ahi + (long)bm * K, Alo + (long)bm * K };
    const __nv_bfloat16* gB[2] = { Bhi + (long)bn * K, Blo + (long)bn * K };

    const int NS = K / 32;

    // ---- stage loader: 4 tiles x 128 rows x 2 chunks of 16B per thread-pass
    auto load_stage = [&](int s) {
        const int k0 = s * 32;
        const uint32_t buf = sbase + (s & 1) * STAGE_B;
#pragma unroll
        for (int t = 0; t < 2; t++) {
#pragma unroll
            for (int j = 0; j < 2; j++) {
                int c = ch + 2 * j;  // 0..3
                cp_async16(buf + t * TILE_B + row * ROWB + c * 16,
                           gA[t] + (long)row * K + k0 + c * 8);
                cp_async16(buf + (2 + t) * TILE_B + row * ROWB + c * 16,
                           gB[t] + (long)row * K + k0 + c * 8);
            }
        }
    };

    load_stage(0);
    CP_COMMIT();

    for (int s = 0; s < NS; s++) {
        if (s + 1 < NS) {
            load_stage(s + 1);
            CP_COMMIT();
            CP_WAIT(1);
        } else {
            CP_WAIT(0);
        }
        __syncthreads();

        const uint32_t buf = sbase + (s & 1) * STAGE_B;
#pragma unroll
        for (int ks = 0; ks < 2; ks++) {
            uint32_t a[2][4][4];
            uint32_t b[2][4][2];
            const int acol = ks * 16 + ((lane >> 4) << 3);
            const int arow = wm * 64 + (lane & 15);
#pragma unroll
            for (int t = 0; t < 2; t++)
#pragma unroll
                for (int mi = 0; mi < 4; mi++)
                    ldsm_x4(a[t][mi][0], a[t][mi][1], a[t][mi][2], a[t][mi][3],
                            buf + t * TILE_B + (arow + mi * 16) * ROWB + acol * 2);
            const int l16  = lane & 15;
            const int bcol = ks * 16 + ((l16 >> 3) << 3);
            const int brow = wn * 32 + (l16 & 7);
#pragma unroll
            for (int t = 0; t < 2; t++)
#pragma unroll
                for (int ni = 0; ni < 4; ni++)
                    ldsm_x2(b[t][ni][0], b[t][ni][1],
                            buf + (2 + t) * TILE_B + (brow + ni * 8) * ROWB + bcol * 2);
#pragma unroll
            for (int mi = 0; mi < 4; mi++)
#pragma unroll
                for (int ni = 0; ni < 4; ni++) {
                    mma16816(acc[mi][ni], a[0][mi], b[0][ni]);  // hi*hi
                    mma16816(acc[mi][ni], a[0][mi], b[1][ni]);  // hi*lo
                    mma16816(acc[mi][ni], a[1][mi], b[0][ni]);  // lo*hi
                }
        }
        __syncthreads();
    }

    // ---- epilogue: fragment rows g/g+8, cols t4*2
    const int g  = lane >> 2;
    const int t4 = lane & 3;
#pragma unroll
    for (int mi = 0; mi < 4; mi++) {
#pragma unroll
        for (int ni = 0; ni < 4; ni++) {
            const int col = bn + wn * 32 + ni * 8 + t4 * 2;
            const long r0 = bm + wm * 64 + mi * 16 + g;
            float2 bb = *(const float2*)&bias[col];
            float2 o0 = { acc[mi][ni][0] + bb.x, acc[mi][ni][1] + bb.y };
            float2 o1 = { acc[mi][ni][2] + bb.x, acc[mi][ni][3] + bb.y };
            *(float2*)&C[r0 * N + col] = o0;
            *(float2*)&C[(r0 + 8) * N + col] = o1;
        }
    }
}

// ---------------------------------------------------------------------------
// Causal flash-attention, fp32 (unchanged).
// ---------------------------------------------------------------------------
#define ATTN_SMEM_BYTES (4 * 64 * 65 * 4)

__global__ void __launch_bounds__(256) attn_kernel(
    const float* __restrict__ qkv, float* __restrict__ out)
{
    extern __shared__ float sm[];
    float (*Qs)[65] = (float (*)[65])sm;
    float (*Ks)[65] = (float (*)[65])(sm + 64 * 65);
    float (*Vs)[65] = (float (*)[65])(sm + 2 * 64 * 65);
    float (*Ps)[65] = (float (*)[65])(sm + 3 * 64 * 65);

    const int tid = threadIdx.x;
    const int qt  = blockIdx.x;
    const int h   = blockIdx.y;
    const int b   = blockIdx.z;
    const int q0  = qt * 64;
    const int tx  = tid & 15;
    const int ty  = tid >> 4;

    const float scale = 0.125f;
    const long base = (long)b * S_ * (3 * NX_);

#pragma unroll
    for (int i = 0; i < 16; i++) {
        int idx = tid + i * 256;
        int r = idx >> 6, d = idx & 63;
        Qs[d][r] = qkv[base + (long)(q0 + r) * (3 * NX_) + h * D_ + d] * scale;
    }

    float m[4], l[4], acc[4][4];
#pragma unroll
    for (int i = 0; i < 4; i++) {
        m[i] = -1e30f; l[i] = 0.f;
#pragma unroll
        for (int j = 0; j < 4; j++) acc[i][j] = 0.f;
    }

    for (int kt = 0; kt <= qt; kt++) {
        __syncthreads();
#pragma unroll
        for (int i = 0; i < 16; i++) {
            int idx = tid + i * 256;
            int r = idx >> 6, d = idx & 63;
            long krow = base + (long)(kt * 64 + r) * (3 * NX_);
            Ks[d][r] = qkv[krow + NX_ + h * D_ + d];
            Vs[r][d] = qkv[krow + 2 * NX_ + h * D_ + d];
        }
        __syncthreads();

        float s[4][4];
#pragma unroll
        for (int i = 0; i < 4; i++)
#pragma unroll
            for (int j = 0; j < 4; j++) s[i][j] = 0.f;

#pragma unroll 8
        for (int d = 0; d < 64; d++) {
            float ra[4], rb[4];
#pragma unroll
            for (int i = 0; i < 4; i++) ra[i] = Qs[d][ty * 4 + i];
#pragma unroll
            for (int j = 0; j < 4; j++) rb[j] = Ks[d][tx * 4 + j];
#pragma unroll
            for (int i = 0; i < 4; i++)
#pragma unroll
                for (int j = 0; j < 4; j++)
                    s[i][j] += ra[i] * rb[j];
        }

        if (kt == qt) {
#pragma unroll
            for (int i = 0; i < 4; i++)
#pragma unroll
                for (int j = 0; j < 4; j++)
                    if (tx * 4 + j > ty * 4 + i) s[i][j] = -1e9f;
        }

#pragma unroll
        for (int i = 0; i < 4; i++) {
            float mx = fmaxf(fmaxf(s[i][0], s[i][1]), fmaxf(s[i][2], s[i][3]));
#pragma unroll
            for (int off = 8; off > 0; off >>= 1)
                mx = fmaxf(mx, __shfl_xor_sync(0xffffffffu, mx, off));
            float mnew = fmaxf(m[i], mx);
            float alpha = __expf(m[i] - mnew);
            m[i] = mnew;
            float rs = 0.f;
#pragma unroll
            for (int j = 0; j < 4; j++) {
                s[i][j] = __expf(s[i][j] - mnew);
                rs += s[i][j];
            }
#pragma unroll
            for (int off = 8; off > 0; off >>= 1)
                rs += __shfl_xor_sync(0xffffffffu, rs, off);
            l[i] = l[i] * alpha + rs;
#pragma unroll
            for (int j = 0; j < 4; j++) {
                acc[i][j] *= alpha;
                Ps[ty * 4 + i][tx * 4 + j] = s[i][j];
            }
        }
        __syncthreads();

#pragma unroll 8
        for (int k = 0; k < 64; k++) {
            float rv[4];
#pragma unroll
            for (int j = 0; j < 4; j++) rv[j] = Vs[k][tx * 4 + j];
#pragma unroll
            for (int i = 0; i < 4; i++) {
                float p = Ps[ty * 4 + i][k];
#pragma unroll
                for (int j = 0; j < 4; j++)
                    acc[i][j] += p * rv[j];
            }
        }
    }

#pragma unroll
    for (int i = 0; i < 4; i++) {
        float inv = 1.f / l[i];
        float4 o;
        o.x = acc[i][0] * inv;
        o.y = acc[i][1] * inv;
        o.z = acc[i][2] * inv;
        o.w = acc[i][3] * inv;
        long row = (long)b * S_ + q0 + ty * 4 + i;
        *(float4*)&out[row * NX_ + h * D_ + tx * 4] = o;
    }
}

// ---------------------------------------------------------------------------
extern "C" void kernel_launch(void* const* d_in, const int* in_sizes, int n_in,
                              void* d_out, int out_size)
{
    const float* x      = (const float*)d_in[0];
    const float* w_attn = (const float*)d_in[1];
    const float* b_attn = (const float*)d_in[2];
    const float* w_proj = (const float*)d_in[3];
    const float* b_proj = (const float*)d_in[4];
    float* out = (float*)d_out;

    float *qkv, *attn;
    __nv_bfloat16 *xhi, *xlo, *ahi, *alo, *wqh, *wql, *wph, *wpl;
    cudaGetSymbolAddress((void**)&qkv, g_qkv);
    cudaGetSymbolAddress((void**)&attn, g_attn);
    cudaGetSymbolAddress((void**)&xhi, g_xhi);
    cudaGetSymbolAddress((void**)&xlo, g_xlo);
    cudaGetSymbolAddress((void**)&ahi, g_ahi);
    cudaGetSymbolAddress((void**)&alo, g_alo);
    cudaGetSymbolAddress((void**)&wqh, g_wqkv_hi);
    cudaGetSymbolAddress((void**)&wql, g_wqkv_lo);
    cudaGetSymbolAddress((void**)&wph, g_wproj_hi);
    cudaGetSymbolAddress((void**)&wpl, g_wproj_lo);

    cudaFuncSetAttribute(attn_kernel,
                         cudaFuncAttributeMaxDynamicSharedMemorySize,
                         ATTN_SMEM_BYTES);
    cudaFuncSetAttribute(gemm_mma,
                         cudaFuncAttributeMaxDynamicSharedMemorySize,
                         GEMM_SMEM_DYN);

    const int M = B_ * S_;  // 8192

    // split x
    {
        int n4 = M * NX_ / 4;
        split_kernel<<<(n4 + 255) / 256, 256>>>(x, xhi, xlo, n4);
    }
    // transpose+split weights
    tsplit_kernel<<<dim3(3 * NX_ / 32, NX_ / 32), dim3(32, 8)>>>(w_attn, wqh, wql, NX_, 3 * NX_);
    tsplit_kernel<<<dim3(NX_ / 32, NX_ / 32), dim3(32, 8)>>>(w_proj, wph, wpl, NX_, NX_);

    // QKV GEMM: [8192,1024] x [1024,3072]^T(weights pre-transposed)
    gemm_mma<<<dim3(3 * NX_ / 128, M / 128), 256, GEMM_SMEM_DYN>>>(
        xhi, xlo, wqh, wql, b_attn, qkv, M, 3 * NX_, NX_);

    // attention
    attn_kernel<<<dim3(S_ / 64, H_, B_), 256, ATTN_SMEM_BYTES>>>(qkv, attn);

    // split attention output
    {
        int n4 = M * NX_ / 4;
        split_kernel<<<(n4 + 255) / 256, 256>>>(attn, ahi, alo, n4);
    }
    // projection GEMM: [8192,1024] x [1024,1024]^T
    gemm_mma<<<dim3(NX_ / 128, M / 128), 256, GEMM_SMEM_DYN>>>(
        ahi, alo, wph, wpl, b_proj, out, M, NX_, NX_);
}

// round 4
// speedup vs baseline: 1.3949x; 1.0014x over previous
#include <cuda_runtime.h>
#include <cuda_bf16.h>
#include <cstdint>

#define B_  8
#define S_  1024
#define NX_ 1024
#define H_  16
#define D_  64

// ---------------- scratch (__device__ globals; no allocation) ----------------
__device__ float g_qkv[B_ * S_ * 3 * NX_];           // [B,S,3*NX] fp32
__device__ float g_attn[B_ * S_ * NX_];              // [B,S,NX]   fp32
__device__ __nv_bfloat16 g_xhi[B_ * S_ * NX_];
__device__ __nv_bfloat16 g_xlo[B_ * S_ * NX_];
__device__ __nv_bfloat16 g_ahi[B_ * S_ * NX_];
__device__ __nv_bfloat16 g_alo[B_ * S_ * NX_];
__device__ __nv_bfloat16 g_wqkv_hi[3 * NX_ * NX_];   // [N=3072, K=1024] (transposed)
__device__ __nv_bfloat16 g_wqkv_lo[3 * NX_ * NX_];
__device__ __nv_bfloat16 g_wproj_hi[NX_ * NX_];      // [N=1024, K=1024]
__device__ __nv_bfloat16 g_wproj_lo[NX_ * NX_];

// ---------------- PTX helpers (baseline ISA only: sm_80-era ops) -------------
__device__ __forceinline__ uint32_t smem_to_u32(const void* p) {
    uint32_t a;
    asm("{ .reg .u64 t; cvta.to.shared.u64 t, %1; cvt.u32.u64 %0, t; }"
        : "=r"(a) : "l"(p));
    return a;
}
__device__ __forceinline__ void cp_async16(uint32_t dst, const void* src) {
    asm volatile("cp.async.cg.shared.global [%0], [%1], 16;"
                 :: "r"(dst), "l"(src) : "memory");
}
#define CP_COMMIT() asm volatile("cp.async.commit_group;" ::: "memory")
#define CP_WAIT(n)  asm volatile("cp.async.wait_group %0;" :: "n"(n) : "memory")

__device__ __forceinline__ void ldsm_x4(uint32_t& r0, uint32_t& r1,
                                        uint32_t& r2, uint32_t& r3, uint32_t addr) {
    asm volatile("ldmatrix.sync.aligned.m8n8.x4.shared.b16 {%0,%1,%2,%3}, [%4];"
                 : "=r"(r0), "=r"(r1), "=r"(r2), "=r"(r3) : "r"(addr));
}
__device__ __forceinline__ void mma16816(float* c, const uint32_t* a, const uint32_t* b) {
    asm volatile("mma.sync.aligned.m16n8k16.row.col.f32.bf16.bf16.f32 "
                 "{%0,%1,%2,%3}, {%4,%5,%6,%7}, {%8,%9}, {%0,%1,%2,%3};"
                 : "+f"(c[0]), "+f"(c[1]), "+f"(c[2]), "+f"(c[3])
                 : "r"(a[0]), "r"(a[1]), "r"(a[2]), "r"(a[3]),
                   "r"(b[0]), "r"(b[1]));
}

// ---------------------------------------------------------------------------
// split: fp32 -> (hi, lo) bf16, same layout. n4 = n/4.
// ---------------------------------------------------------------------------
__global__ void split_kernel(const float* __restrict__ in,
                             __nv_bfloat16* __restrict__ hi,
                             __nv_bfloat16* __restrict__ lo, int n4)
{
    int i = blockIdx.x * blockDim.x + threadIdx.x;
    if (i >= n4) return;
    float4 v = ((const float4*)in)[i];
    __nv_bfloat16 h0 = __float2bfloat16(v.x);
    __nv_bfloat16 h1 = __float2bfloat16(v.y);
    __nv_bfloat16 h2 = __float2bfloat16(v.z);
    __nv_bfloat16 h3 = __float2bfloat16(v.w);
    __nv_bfloat16 l0 = __float2bfloat16(v.x - __bfloat162float(h0));
    __nv_bfloat16 l1 = __float2bfloat16(v.y - __bfloat162float(h1));
    __nv_bfloat16 l2 = __float2bfloat16(v.z - __bfloat162float(h2));
    __nv_bfloat16 l3 = __float2bfloat16(v.w - __bfloat162float(h3));
    ((__nv_bfloat162*)hi)[2 * i]     = __nv_bfloat162(h0, h1);
    ((__nv_bfloat162*)hi)[2 * i + 1] = __nv_bfloat162(h2, h3);
    ((__nv_bfloat162*)lo)[2 * i]     = __nv_bfloat162(l0, l1);
    ((__nv_bfloat162*)lo)[2 * i + 1] = __nv_bfloat162(l2, l3);
}

// ---------------------------------------------------------------------------
// transpose + split: W[K,N] fp32 -> T_hi/T_lo [N,K] bf16
// ---------------------------------------------------------------------------
__global__ void tsplit_kernel(const float* __restrict__ W,
                              __nv_bfloat16* __restrict__ Thi,
                              __nv_bfloat16* __restrict__ Tlo, int K, int N)
{
    __shared__ float t[32][33];
    int n0 = blockIdx.x * 32, k0 = blockIdx.y * 32;
    int tx = threadIdx.x, ty = threadIdx.y;  // 32 x 8
#pragma unroll
    for (int i = 0; i < 4; i++)
        t[ty + i * 8][tx] = W[(long)(k0 + ty + i * 8) * N + n0 + tx];
    __syncthreads();
#pragma unroll
    for (int i = 0; i < 4; i++) {
        float v = t[tx][ty + i * 8];
        __nv_bfloat16 h = __float2bfloat16(v);
        __nv_bfloat16 l = __float2bfloat16(v - __bfloat162float(h));
        long o = (long)(n0 + ty + i * 8) * K + k0 + tx;
        Thi[o] = h;
        Tlo[o] = l;
    }
}

// ---------------------------------------------------------------------------
// bf16-split GEMM on mma.sync (HMMA):
//   C[M,N] = Ahi/lo[M,K] x (Bhi/lo[N,K])^T + bias[N]
// 128x128x32 tiles, 256 threads (8 warps: 2 along M x 4 along N, 64x32 each),
// 3-stage cp.async pipeline, product-outermost MMA ordering.
// ---------------------------------------------------------------------------
#define ROWB    80                       // 32 bf16 (64B) + 16B pad, 16B-aligned
#define TILE_B  (128 * ROWB)             // 10240 B
#define STAGE_B (4 * TILE_B)             // Ahi Alo Bhi Blo = 40960 B
#define NSTAGE  3
#define GEMM_SMEM_DYN (NSTAGE * STAGE_B) // 122880 B

__global__ void __launch_bounds__(256, 1) gemm_mma(
    const __nv_bfloat16* __restrict__ Ahi, const __nv_bfloat16* __restrict__ Alo,
    const __nv_bfloat16* __restrict__ Bhi, const __nv_bfloat16* __restrict__ Blo,
    const float* __restrict__ bias, float* __restrict__ C,
    int M, int N, int K)
{
    extern __shared__ __align__(128) char smem[];
    const uint32_t sbase = smem_to_u32(smem);

    const int tid  = threadIdx.x;
    const int lane = tid & 31;
    const int wid  = tid >> 5;
    const int wm   = wid & 1;        // 2 warps along M
    const int wn   = wid >> 1;       // 4 warps along N
    const int bm   = blockIdx.y * 128;
    const int bn   = blockIdx.x * 128;

    float acc[4][4][4];
#pragma unroll
    for (int mi = 0; mi < 4; mi++)
#pragma unroll
        for (int ni = 0; ni < 4; ni++)
#pragma unroll
            for (int r = 0; r < 4; r++) acc[mi][ni][r] = 0.f;

    const int row = tid & 127;       // smem tile row this thread fills
    const int ch  = tid >> 7;        // chunk pair base (0 or 1); +2 on j=1

    const __nv_bfloat16* gA[2] = { Ahi + (long)bm * K, Alo + (long)bm * K };
    const __nv_bfloat16* gB[2] = { Bhi + (long)bn * K, Blo + (long)bn * K };

    const int NS = K / 32;

    auto load_stage = [&](int s) {
        const int k0 = s * 32;
        const uint32_t buf = sbase + (s % NSTAGE) * STAGE_B;
#pragma unroll
        for (int t = 0; t < 2; t++) {
#pragma unroll
            for (int j = 0; j < 2; j++) {
                int c = ch + 2 * j;  // 0..3
                cp_async16(buf + t * TILE_B + row * ROWB + c * 16,
                           gA[t] + (long)row * K + k0 + c * 8);
                cp_async16(buf + (2 + t) * TILE_B + row * ROWB + c * 16,
                           gB[t] + (long)row * K + k0 + c * 8);
            }
        }
    };

    load_stage(0);
    CP_COMMIT();
    load_stage(1);
    CP_COMMIT();

    // ldmatrix addressing
    const int arow  = wm * 64 + (lane & 15);
    const int asel  = (lane >> 4) << 3;                     // k-half for A x4
    const int brow  = wn * 32 + (lane & 7) + ((lane >> 4) << 3);  // n row
    const int bsel  = ((lane >> 3) & 1) << 3;               // k-half for B x4

    for (int s = 0; s < NS; s++) {
        if (s + 2 < NS) load_stage(s + 2);
        CP_COMMIT();
        CP_WAIT(2);
        __syncthreads();

        const uint32_t buf = sbase + (s % NSTAGE) * STAGE_B;
#pragma unroll
        for (int ks = 0; ks < 2; ks++) {
            uint32_t a[2][4][4];
            uint32_t b[2][4][2];
            const int acol = ks * 16 + asel;
#pragma unroll
            for (int t = 0; t < 2; t++)
#pragma unroll
                for (int mi = 0; mi < 4; mi++)
                    ldsm_x4(a[t][mi][0], a[t][mi][1], a[t][mi][2], a[t][mi][3],
                            buf + t * TILE_B + (arow + mi * 16) * ROWB + acol * 2);
            const int bcol = ks * 16 + bsel;
#pragma unroll
            for (int t = 0; t < 2; t++)
#pragma unroll
                for (int nj = 0; nj < 2; nj++)
                    ldsm_x4(b[t][nj * 2][0], b[t][nj * 2][1],
                            b[t][nj * 2 + 1][0], b[t][nj * 2 + 1][1],
                            buf + (2 + t) * TILE_B + (brow + nj * 16) * ROWB + bcol * 2);

            // product-outermost: consecutive MMAs hit independent accumulators
#pragma unroll
            for (int p = 0; p < 3; p++) {
                const int at = (p == 2) ? 1 : 0;
                const int bt = (p == 1) ? 1 : 0;
#pragma unroll
                for (int mi = 0; mi < 4; mi++)
#pragma unroll
                    for (int ni = 0; ni < 4; ni++)
                        mma16816(acc[mi][ni], a[at][mi], b[bt][ni]);
            }
        }
        __syncthreads();
    }

    // ---- epilogue: fragment rows g/g+8, cols t4*2
    const int g  = lane >> 2;
    const int t4 = lane & 3;
#pragma unroll
    for (int mi = 0; mi < 4; mi++) {
#pragma unroll
        for (int ni = 0; ni < 4; ni++) {
            const int col = bn + wn * 32 + ni * 8 + t4 * 2;
            const long r0 = bm + wm * 64 + mi * 16 + g;
            float2 bb = *(const float2*)&bias[col];
            float2 o0 = { acc[mi][ni][0] + bb.x, acc[mi][ni][1] + bb.y };
            float2 o1 = { acc[mi][ni][2] + bb.x, acc[mi][ni][3] + bb.y };
            *(float2*)&C[r0 * N + col] = o0;
            *(float2*)&C[(r0 + 8) * N + col] = o1;
        }
    }
}

// ---------------------------------------------------------------------------
// Causal flash-attention, fp32 (unchanged).
// ---------------------------------------------------------------------------
#define ATTN_SMEM_BYTES (4 * 64 * 65 * 4)

__global__ void __launch_bounds__(256) attn_kernel(
    const float* __restrict__ qkv, float* __restrict__ out)
{
    extern __shared__ float sm[];
    float (*Qs)[65] = (float (*)[65])sm;
    float (*Ks)[65] = (float (*)[65])(sm + 64 * 65);
    float (*Vs)[65] = (float (*)[65])(sm + 2 * 64 * 65);
    float (*Ps)[65] = (float (*)[65])(sm + 3 * 64 * 65);

    const int tid = threadIdx.x;
    const int qt  = blockIdx.x;
    const int h   = blockIdx.y;
    const int b   = blockIdx.z;
    const int q0  = qt * 64;
    const int tx  = tid & 15;
    const int ty  = tid >> 4;

    const float scale = 0.125f;
    const long base = (long)b * S_ * (3 * NX_);

#pragma unroll
    for (int i = 0; i < 16; i++) {
        int idx = tid + i * 256;
        int r = idx >> 6, d = idx & 63;
        Qs[d][r] = qkv[base + (long)(q0 + r) * (3 * NX_) + h * D_ + d] * scale;
    }

    float m[4], l[4], acc[4][4];
#pragma unroll
    for (int i = 0; i < 4; i++) {
        m[i] = -1e30f; l[i] = 0.f;
#pragma unroll
        for (int j = 0; j < 4; j++) acc[i][j] = 0.f;
    }

    for (int kt = 0; kt <= qt; kt++) {
        __syncthreads();
#pragma unroll
        for (int i = 0; i < 16; i++) {
            int idx = tid + i * 256;
            int r = idx >> 6, d = idx & 63;
            long krow = base + (long)(kt * 64 + r) * (3 * NX_);
            Ks[d][r] = qkv[krow + NX_ + h * D_ + d];
            Vs[r][d] = qkv[krow + 2 * NX_ + h * D_ + d];
        }
        __syncthreads();

        float s[4][4];
#pragma unroll
        for (int i = 0; i < 4; i++)
#pragma unroll
            for (int j = 0; j < 4; j++) s[i][j] = 0.f;

#pragma unroll 8
        for (int d = 0; d < 64; d++) {
            float ra[4], rb[4];
#pragma unroll
            for (int i = 0; i < 4; i++) ra[i] = Qs[d][ty * 4 + i];
#pragma unroll
            for (int j = 0; j < 4; j++) rb[j] = Ks[d][tx * 4 + j];
#pragma unroll
            for (int i = 0; i < 4; i++)
#pragma unroll
                for (int j = 0; j < 4; j++)
                    s[i][j] += ra[i] * rb[j];
        }

        if (kt == qt) {
#pragma unroll
            for (int i = 0; i < 4; i++)
#pragma unroll
                for (int j = 0; j < 4; j++)
                    if (tx * 4 + j > ty * 4 + i) s[i][j] = -1e9f;
        }

#pragma unroll
        for (int i = 0; i < 4; i++) {
            float mx = fmaxf(fmaxf(s[i][0], s[i][1]), fmaxf(s[i][2], s[i][3]));
#pragma unroll
            for (int off = 8; off > 0; off >>= 1)
                mx = fmaxf(mx, __shfl_xor_sync(0xffffffffu, mx, off));
            float mnew = fmaxf(m[i], mx);
            float alpha = __expf(m[i] - mnew);
            m[i] = mnew;
            float rs = 0.f;
#pragma unroll
            for (int j = 0; j < 4; j++) {
                s[i][j] = __expf(s[i][j] - mnew);
                rs += s[i][j];
            }
#pragma unroll
            for (int off = 8; off > 0; off >>= 1)
                rs += __shfl_xor_sync(0xffffffffu, rs, off);
            l[i] = l[i] * alpha + rs;
#pragma unroll
            for (int j = 0; j < 4; j++) {
                acc[i][j] *= alpha;
                Ps[ty * 4 + i][tx * 4 + j] = s[i][j];
            }
        }
        __syncthreads();

#pragma unroll 8
        for (int k = 0; k < 64; k++) {
            float rv[4];
#pragma unroll
            for (int j = 0; j < 4; j++) rv[j] = Vs[k][tx * 4 + j];
#pragma unroll
            for (int i = 0; i < 4; i++) {
                float p = Ps[ty * 4 + i][k];
#pragma unroll
                for (int j = 0; j < 4; j++)
                    acc[i][j] += p * rv[j];
            }
        }
    }

#pragma unroll
    for (int i = 0; i < 4; i++) {
        float inv = 1.f / l[i];
        float4 o;
        o.x = acc[i][0] * inv;
        o.y = acc[i][1] * inv;
        o.z = acc[i][2] * inv;
        o.w = acc[i][3] * inv;
        long row = (long)b * S_ + q0 + ty * 4 + i;
        *(float4*)&out[row * NX_ + h * D_ + tx * 4] = o;
    }
}

// ---------------------------------------------------------------------------
extern "C" void kernel_launch(void* const* d_in, const int* in_sizes, int n_in,
                              void* d_out, int out_size)
{
    const float* x      = (const float*)d_in[0];
    const float* w_attn = (const float*)d_in[1];
    const float* b_attn = (const float*)d_in[2];
    const float* w_proj = (const float*)d_in[3];
    const float* b_proj = (const float*)d_in[4];
    float* out = (float*)d_out;

    float *qkv, *attn;
    __nv_bfloat16 *xhi, *xlo, *ahi, *alo, *wqh, *wql, *wph, *wpl;
    cudaGetSymbolAddress((void**)&qkv, g_qkv);
    cudaGetSymbolAddress((void**)&attn, g_attn);
    cudaGetSymbolAddress((void**)&xhi, g_xhi);
    cudaGetSymbolAddress((void**)&xlo, g_xlo);
    cudaGetSymbolAddress((void**)&ahi, g_ahi);
    cudaGetSymbolAddress((void**)&alo, g_alo);
    cudaGetSymbolAddress((void**)&wqh, g_wqkv_hi);
    cudaGetSymbolAddress((void**)&wql, g_wqkv_lo);
    cudaGetSymbolAddress((void**)&wph, g_wproj_hi);
    cudaGetSymbolAddress((void**)&wpl, g_wproj_lo);

    cudaFuncSetAttribute(attn_kernel,
                         cudaFuncAttributeMaxDynamicSharedMemorySize,
                         ATTN_SMEM_BYTES);
    cudaFuncSetAttribute(gemm_mma,
                         cudaFuncAttributeMaxDynamicSharedMemorySize,
                         GEMM_SMEM_DYN);

    const int M = B_ * S_;  // 8192

    // split x
    {
        int n4 = M * NX_ / 4;
        split_kernel<<<(n4 + 255) / 256, 256>>>(x, xhi, xlo, n4);
    }
    // transpose+split weights
    tsplit_kernel<<<dim3(3 * NX_ / 32, NX_ / 32), dim3(32, 8)>>>(w_attn, wqh, wql, NX_, 3 * NX_);
    tsplit_kernel<<<dim3(NX_ / 32, NX_ / 32), dim3(32, 8)>>>(w_proj, wph, wpl, NX_, NX_);

    // QKV GEMM: [8192,1024] x [1024,3072]^T (weights pre-transposed)
    gemm_mma<<<dim3(3 * NX_ / 128, M / 128), 256, GEMM_SMEM_DYN>>>(
        xhi, xlo, wqh, wql, b_attn, qkv, M, 3 * NX_, NX_);

    // attention
    attn_kernel<<<dim3(S_ / 64, H_, B_), 256, ATTN_SMEM_BYTES>>>(qkv, attn);

    // split attention output
    {
        int n4 = M * NX_ / 4;
        split_kernel<<<(n4 + 255) / 256, 256>>>(attn, ahi, alo, n4);
    }
    // projection GEMM: [8192,1024] x [1024,1024]^T
    gemm_mma<<<dim3(NX_ / 128, M / 128), 256, GEMM_SMEM_DYN>>>(
        ahi, alo, wph, wpl, b_proj, out, M, NX_, NX_);
}

// round 5
// speedup vs baseline: 1.5149x; 1.0861x over previous
#include <cuda_runtime.h>
#include <cuda_bf16.h>
#include <cstdint>

#define B_  8
#define S_  1024
#define NX_ 1024
#define H_  16
#define D_  64

// ---------------- scratch (__device__ globals; no allocation) ----------------
__device__ float g_qkv[B_ * S_ * 3 * NX_];           // [B,S,3*NX] fp32
__device__ float g_attn[B_ * S_ * NX_];              // [B,S,NX]   fp32
__device__ __nv_bfloat16 g_xhi[B_ * S_ * NX_];
__device__ __nv_bfloat16 g_xlo[B_ * S_ * NX_];
__device__ __nv_bfloat16 g_ahi[B_ * S_ * NX_];
__device__ __nv_bfloat16 g_alo[B_ * S_ * NX_];
__device__ __nv_bfloat16 g_wqkv_hi[3 * NX_ * NX_];   // [N=3072, K=1024] (transposed)
__device__ __nv_bfloat16 g_wqkv_lo[3 * NX_ * NX_];
__device__ __nv_bfloat16 g_wproj_hi[NX_ * NX_];      // [N=1024, K=1024]
__device__ __nv_bfloat16 g_wproj_lo[NX_ * NX_];

// ---------------- PTX helpers (baseline ISA only: sm_80-era ops) -------------
__device__ __forceinline__ uint32_t smem_to_u32(const void* p) {
    uint32_t a;
    asm("{ .reg .u64 t; cvta.to.shared.u64 t, %1; cvt.u32.u64 %0, t; }"
        : "=r"(a) : "l"(p));
    return a;
}
__device__ __forceinline__ void cp_async16(uint32_t dst, const void* src) {
    asm volatile("cp.async.cg.shared.global [%0], [%1], 16;"
                 :: "r"(dst), "l"(src) : "memory");
}
#define CP_COMMIT() asm volatile("cp.async.commit_group;" ::: "memory")
#define CP_WAIT(n)  asm volatile("cp.async.wait_group %0;" :: "n"(n) : "memory")

__device__ __forceinline__ void ldsm_x4(uint32_t& r0, uint32_t& r1,
                                        uint32_t& r2, uint32_t& r3, uint32_t addr) {
    asm volatile("ldmatrix.sync.aligned.m8n8.x4.shared.b16 {%0,%1,%2,%3}, [%4];"
                 : "=r"(r0), "=r"(r1), "=r"(r2), "=r"(r3) : "r"(addr));
}
__device__ __forceinline__ void mma16816(float* c, const uint32_t* a, const uint32_t* b) {
    asm volatile("mma.sync.aligned.m16n8k16.row.col.f32.bf16.bf16.f32 "
                 "{%0,%1,%2,%3}, {%4,%5,%6,%7}, {%8,%9}, {%0,%1,%2,%3};"
                 : "+f"(c[0]), "+f"(c[1]), "+f"(c[2]), "+f"(c[3])
                 : "r"(a[0]), "r"(a[1]), "r"(a[2]), "r"(a[3]),
                   "r"(b[0]), "r"(b[1]));
}

// ---------------------------------------------------------------------------
// split: fp32 -> (hi, lo) bf16, same layout. n4 = n/4.
// ---------------------------------------------------------------------------
__global__ void split_kernel(const float* __restrict__ in,
                             __nv_bfloat16* __restrict__ hi,
                             __nv_bfloat16* __restrict__ lo, int n4)
{
    int i = blockIdx.x * blockDim.x + threadIdx.x;
    if (i >= n4) return;
    float4 v = ((const float4*)in)[i];
    __nv_bfloat16 h0 = __float2bfloat16(v.x);
    __nv_bfloat16 h1 = __float2bfloat16(v.y);
    __nv_bfloat16 h2 = __float2bfloat16(v.z);
    __nv_bfloat16 h3 = __float2bfloat16(v.w);
    __nv_bfloat16 l0 = __float2bfloat16(v.x - __bfloat162float(h0));
    __nv_bfloat16 l1 = __float2bfloat16(v.y - __bfloat162float(h1));
    __nv_bfloat16 l2 = __float2bfloat16(v.z - __bfloat162float(h2));
    __nv_bfloat16 l3 = __float2bfloat16(v.w - __bfloat162float(h3));
    ((__nv_bfloat162*)hi)[2 * i]     = __nv_bfloat162(h0, h1);
    ((__nv_bfloat162*)hi)[2 * i + 1] = __nv_bfloat162(h2, h3);
    ((__nv_bfloat162*)lo)[2 * i]     = __nv_bfloat162(l0, l1);
    ((__nv_bfloat162*)lo)[2 * i + 1] = __nv_bfloat162(l2, l3);
}

// ---------------------------------------------------------------------------
// transpose + split: W[K,N] fp32 -> T_hi/T_lo [N,K] bf16
// ---------------------------------------------------------------------------
__global__ void tsplit_kernel(const float* __restrict__ W,
                              __nv_bfloat16* __restrict__ Thi,
                              __nv_bfloat16* __restrict__ Tlo, int K, int N)
{
    __shared__ float t[32][33];
    int n0 = blockIdx.x * 32, k0 = blockIdx.y * 32;
    int tx = threadIdx.x, ty = threadIdx.y;  // 32 x 8
#pragma unroll
    for (int i = 0; i < 4; i++)
        t[ty + i * 8][tx] = W[(long)(k0 + ty + i * 8) * N + n0 + tx];
    __syncthreads();
#pragma unroll
    for (int i = 0; i < 4; i++) {
        float v = t[tx][ty + i * 8];
        __nv_bfloat16 h = __float2bfloat16(v);
        __nv_bfloat16 l = __float2bfloat16(v - __bfloat162float(h));
        long o = (long)(n0 + ty + i * 8) * K + k0 + tx;
        Thi[o] = h;
        Tlo[o] = l;
    }
}

// ---------------------------------------------------------------------------
// bf16-split GEMM on mma.sync (HMMA):
//   C[M,N] = Ahi/lo[M,K] x (Bhi/lo[N,K])^T + bias[N]
// 128x128x32 tiles, 256 threads (8 warps: 2 along M x 4 along N, 64x32 each),
// 2-stage cp.async pipeline, 2 CTAs/SM for cross-CTA phase overlap.
// ---------------------------------------------------------------------------
#define ROWB    80                       // 32 bf16 (64B) + 16B pad, 16B-aligned
#define TILE_B  (128 * ROWB)             // 10240 B
#define STAGE_B (4 * TILE_B)             // Ahi Alo Bhi Blo = 40960 B
#define NSTAGE  2
#define GEMM_SMEM_DYN (NSTAGE * STAGE_B) // 81920 B -> 2 CTAs/SM (160KB)

__global__ void __launch_bounds__(256, 2) gemm_mma(
    const __nv_bfloat16* __restrict__ Ahi, const __nv_bfloat16* __restrict__ Alo,
    const __nv_bfloat16* __restrict__ Bhi, const __nv_bfloat16* __restrict__ Blo,
    const float* __restrict__ bias, float* __restrict__ C,
    int M, int N, int K)
{
    extern __shared__ __align__(128) char smem[];
    const uint32_t sbase = smem_to_u32(smem);

    const int tid  = threadIdx.x;
    const int lane = tid & 31;
    const int wid  = tid >> 5;
    const int wm   = wid & 1;        // 2 warps along M
    const int wn   = wid >> 1;       // 4 warps along N
    const int bm   = blockIdx.y * 128;
    const int bn   = blockIdx.x * 128;

    float acc[4][4][4];
#pragma unroll
    for (int mi = 0; mi < 4; mi++)
#pragma unroll
        for (int ni = 0; ni < 4; ni++)
#pragma unroll
            for (int r = 0; r < 4; r++) acc[mi][ni][r] = 0.f;

    const int row = tid & 127;       // smem tile row this thread fills
    const int ch  = tid >> 7;        // chunk pair base (0 or 1); +2 on j=1

    const __nv_bfloat16* gA[2] = { Ahi + (long)bm * K, Alo + (long)bm * K };
    const __nv_bfloat16* gB[2] = { Bhi + (long)bn * K, Blo + (long)bn * K };

    const int NS = K / 32;

    auto load_stage = [&](int s) {
        const int k0 = s * 32;
        const uint32_t buf = sbase + (s & 1) * STAGE_B;
#pragma unroll
        for (int t = 0; t < 2; t++) {
#pragma unroll
            for (int j = 0; j < 2; j++) {
                int c = ch + 2 * j;  // 0..3
                cp_async16(buf + t * TILE_B + row * ROWB + c * 16,
                           gA[t] + (long)row * K + k0 + c * 8);
                cp_async16(buf + (2 + t) * TILE_B + row * ROWB + c * 16,
                           gB[t] + (long)row * K + k0 + c * 8);
            }
        }
    };

    load_stage(0);
    CP_COMMIT();

    // ldmatrix addressing
    const int arow  = wm * 64 + (lane & 15);
    const int asel  = (lane >> 4) << 3;                           // k-half for A x4
    const int brow  = wn * 32 + (lane & 7) + ((lane >> 4) << 3);  // n row
    const int bsel  = ((lane >> 3) & 1) << 3;                     // k-half for B x4

    for (int s = 0; s < NS; s++) {
        if (s + 1 < NS) {
            load_stage(s + 1);
            CP_COMMIT();
            CP_WAIT(1);
        } else {
            CP_WAIT(0);
        }
        __syncthreads();

        const uint32_t buf = sbase + (s & 1) * STAGE_B;
#pragma unroll
        for (int ks = 0; ks < 2; ks++) {
            uint32_t a[4][4];          // one A tile at a time (reg pressure)
            uint32_t b[2][4][2];
            const int acol = ks * 16 + asel;
            const int bcol = ks * 16 + bsel;
#pragma unroll
            for (int t = 0; t < 2; t++)
#pragma unroll
                for (int nj = 0; nj < 2; nj++)
                    ldsm_x4(b[t][nj * 2][0], b[t][nj * 2][1],
                            b[t][nj * 2 + 1][0], b[t][nj * 2 + 1][1],
                            buf + (2 + t) * TILE_B + (brow + nj * 16) * ROWB + bcol * 2);

            // A-hi fragments: products hi*hi and hi*lo
#pragma unroll
            for (int mi = 0; mi < 4; mi++)
                ldsm_x4(a[mi][0], a[mi][1], a[mi][2], a[mi][3],
                        buf + 0 * TILE_B + (arow + mi * 16) * ROWB + acol * 2);
#pragma unroll
            for (int mi = 0; mi < 4; mi++)
#pragma unroll
                for (int ni = 0; ni < 4; ni++)
                    mma16816(acc[mi][ni], a[mi], b[0][ni]);   // hi*hi
#pragma unroll
            for (int mi = 0; mi < 4; mi++)
#pragma unroll
                for (int ni = 0; ni < 4; ni++)
                    mma16816(acc[mi][ni], a[mi], b[1][ni]);   // hi*lo

            // A-lo fragments: product lo*hi
#pragma unroll
            for (int mi = 0; mi < 4; mi++)
                ldsm_x4(a[mi][0], a[mi][1], a[mi][2], a[mi][3],
                        buf + 1 * TILE_B + (arow + mi * 16) * ROWB + acol * 2);
#pragma unroll
            for (int mi = 0; mi < 4; mi++)
#pragma unroll
                for (int ni = 0; ni < 4; ni++)
                    mma16816(acc[mi][ni], a[mi], b[0][ni]);   // lo*hi
        }
        __syncthreads();
    }

    // ---- epilogue: fragment rows g/g+8, cols t4*2
    const int g  = lane >> 2;
    const int t4 = lane & 3;
#pragma unroll
    for (int mi = 0; mi < 4; mi++) {
#pragma unroll
        for (int ni = 0; ni < 4; ni++) {
            const int col = bn + wn * 32 + ni * 8 + t4 * 2;
            const long r0 = bm + wm * 64 + mi * 16 + g;
            float2 bb = *(const float2*)&bias[col];
            float2 o0 = { acc[mi][ni][0] + bb.x, acc[mi][ni][1] + bb.y };
            float2 o1 = { acc[mi][ni][2] + bb.x, acc[mi][ni][3] + bb.y };
            *(float2*)&C[r0 * N + col] = o0;
            *(float2*)&C[(r0 + 8) * N + col] = o1;
        }
    }
}

// ---------------------------------------------------------------------------
// Causal flash-attention, fp32 (unchanged).
// ---------------------------------------------------------------------------
#define ATTN_SMEM_BYTES (4 * 64 * 65 * 4)

__global__ void __launch_bounds__(256) attn_kernel(
    const float* __restrict__ qkv, float* __restrict__ out)
{
    extern __shared__ float sm[];
    float (*Qs)[65] = (float (*)[65])sm;
    float (*Ks)[65] = (float (*)[65])(sm + 64 * 65);
    float (*Vs)[65] = (float (*)[65])(sm + 2 * 64 * 65);
    float (*Ps)[65] = (float (*)[65])(sm + 3 * 64 * 65);

    const int tid = threadIdx.x;
    const int qt  = blockIdx.x;
    const int h   = blockIdx.y;
    const int b   = blockIdx.z;
    const int q0  = qt * 64;
    const int tx  = tid & 15;
    const int ty  = tid >> 4;

    const float scale = 0.125f;
    const long base = (long)b * S_ * (3 * NX_);

#pragma unroll
    for (int i = 0; i < 16; i++) {
        int idx = tid + i * 256;
        int r = idx >> 6, d = idx & 63;
        Qs[d][r] = qkv[base + (long)(q0 + r) * (3 * NX_) + h * D_ + d] * scale;
    }

    float m[4], l[4], acc[4][4];
#pragma unroll
    for (int i = 0; i < 4; i++) {
        m[i] = -1e30f; l[i] = 0.f;
#pragma unroll
        for (int j = 0; j < 4; j++) acc[i][j] = 0.f;
    }

    for (int kt = 0; kt <= qt; kt++) {
        __syncthreads();
#pragma unroll
        for (int i = 0; i < 16; i++) {
            int idx = tid + i * 256;
            int r = idx >> 6, d = idx & 63;
            long krow = base + (long)(kt * 64 + r) * (3 * NX_);
            Ks[d][r] = qkv[krow + NX_ + h * D_ + d];
            Vs[r][d] = qkv[krow + 2 * NX_ + h * D_ + d];
        }
        __syncthreads();

        float s[4][4];
#pragma unroll
        for (int i = 0; i < 4; i++)
#pragma unroll
            for (int j = 0; j < 4; j++) s[i][j] = 0.f;

#pragma unroll 8
        for (int d = 0; d < 64; d++) {
            float ra[4], rb[4];
#pragma unroll
            for (int i = 0; i < 4; i++) ra[i] = Qs[d][ty * 4 + i];
#pragma unroll
            for (int j = 0; j < 4; j++) rb[j] = Ks[d][tx * 4 + j];
#pragma unroll
            for (int i = 0; i < 4; i++)
#pragma unroll
                for (int j = 0; j < 4; j++)
                    s[i][j] += ra[i] * rb[j];
        }

        if (kt == qt) {
#pragma unroll
            for (int i = 0; i < 4; i++)
#pragma unroll
                for (int j = 0; j < 4; j++)
                    if (tx * 4 + j > ty * 4 + i) s[i][j] = -1e9f;
        }

#pragma unroll
        for (int i = 0; i < 4; i++) {
            float mx = fmaxf(fmaxf(s[i][0], s[i][1]), fmaxf(s[i][2], s[i][3]));
#pragma unroll
            for (int off = 8; off > 0; off >>= 1)
                mx = fmaxf(mx, __shfl_xor_sync(0xffffffffu, mx, off));
            float mnew = fmaxf(m[i], mx);
            float alpha = __expf(m[i] - mnew);
            m[i] = mnew;
            float rs = 0.f;
#pragma unroll
            for (int j = 0; j < 4; j++) {
                s[i][j] = __expf(s[i][j] - mnew);
                rs += s[i][j];
            }
#pragma unroll
            for (int off = 8; off > 0; off >>= 1)
                rs += __shfl_xor_sync(0xffffffffu, rs, off);
            l[i] = l[i] * alpha + rs;
#pragma unroll
            for (int j = 0; j < 4; j++) {
                acc[i][j] *= alpha;
                Ps[ty * 4 + i][tx * 4 + j] = s[i][j];
            }
        }
        __syncthreads();

#pragma unroll 8
        for (int k = 0; k < 64; k++) {
            float rv[4];
#pragma unroll
            for (int j = 0; j < 4; j++) rv[j] = Vs[k][tx * 4 + j];
#pragma unroll
            for (int i = 0; i < 4; i++) {
                float p = Ps[ty * 4 + i][k];
#pragma unroll
                for (int j = 0; j < 4; j++)
                    acc[i][j] += p * rv[j];
            }
        }
    }

#pragma unroll
    for (int i = 0; i < 4; i++) {
        float inv = 1.f / l[i];
        float4 o;
        o.x = acc[i][0] * inv;
        o.y = acc[i][1] * inv;
        o.z = acc[i][2] * inv;
        o.w = acc[i][3] * inv;
        long row = (long)b * S_ + q0 + ty * 4 + i;
        *(float4*)&out[row * NX_ + h * D_ + tx * 4] = o;
    }
}

// ---------------------------------------------------------------------------
extern "C" void kernel_launch(void* const* d_in, const int* in_sizes, int n_in,
                              void* d_out, int out_size)
{
    const float* x      = (const float*)d_in[0];
    const float* w_attn = (const float*)d_in[1];
    const float* b_attn = (const float*)d_in[2];
    const float* w_proj = (const float*)d_in[3];
    const float* b_proj = (const float*)d_in[4];
    float* out = (float*)d_out;

    float *qkv, *attn;
    __nv_bfloat16 *xhi, *xlo, *ahi, *alo, *wqh, *wql, *wph, *wpl;
    cudaGetSymbolAddress((void**)&qkv, g_qkv);
    cudaGetSymbolAddress((void**)&attn, g_attn);
    cudaGetSymbolAddress((void**)&xhi, g_xhi);
    cudaGetSymbolAddress((void**)&xlo, g_xlo);
    cudaGetSymbolAddress((void**)&ahi, g_ahi);
    cudaGetSymbolAddress((void**)&alo, g_alo);
    cudaGetSymbolAddress((void**)&wqh, g_wqkv_hi);
    cudaGetSymbolAddress((void**)&wql, g_wqkv_lo);
    cudaGetSymbolAddress((void**)&wph, g_wproj_hi);
    cudaGetSymbolAddress((void**)&wpl, g_wproj_lo);

    cudaFuncSetAttribute(attn_kernel,
                         cudaFuncAttributeMaxDynamicSharedMemorySize,
                         ATTN_SMEM_BYTES);
    cudaFuncSetAttribute(gemm_mma,
                         cudaFuncAttributeMaxDynamicSharedMemorySize,
                         GEMM_SMEM_DYN);

    const int M = B_ * S_;  // 8192

    // split x
    {
        int n4 = M * NX_ / 4;
        split_kernel<<<(n4 + 255) / 256, 256>>>(x, xhi, xlo, n4);
    }
    // transpose+split weights
    tsplit_kernel<<<dim3(3 * NX_ / 32, NX_ / 32), dim3(32, 8)>>>(w_attn, wqh, wql, NX_, 3 * NX_);
    tsplit_kernel<<<dim3(NX_ / 32, NX_ / 32), dim3(32, 8)>>>(w_proj, wph, wpl, NX_, NX_);

    // QKV GEMM: [8192,1024] x [1024,3072]^T (weights pre-transposed)
    gemm_mma<<<dim3(3 * NX_ / 128, M / 128), 256, GEMM_SMEM_DYN>>>(
        xhi, xlo, wqh, wql, b_attn, qkv, M, 3 * NX_, NX_);

    // attention
    attn_kernel<<<dim3(S_ / 64, H_, B_), 256, ATTN_SMEM_BYTES>>>(qkv, attn);

    // split attention output
    {
        int n4 = M * NX_ / 4;
        split_kernel<<<(n4 + 255) / 256, 256>>>(attn, ahi, alo, n4);
    }
    // projection GEMM: [8192,1024] x [1024,1024]^T
    gemm_mma<<<dim3(NX_ / 128, M / 128), 256, GEMM_SMEM_DYN>>>(
        ahi, alo, wph, wpl, b_proj, out, M, NX_, NX_);
}

// round 6
// speedup vs baseline: 1.7425x; 1.1502x over previous
#include <cuda_runtime.h>
#include <cuda_bf16.h>
#include <cstdint>

#define B_  8
#define S_  1024
#define NX_ 1024
#define H_  16
#define D_  64

// ---------------- scratch (__device__ globals; no allocation) ----------------
__device__ float g_qkv[B_ * S_ * 3 * NX_];           // [B,S,3*NX] fp32
__device__ float g_attn[B_ * S_ * NX_];              // [B,S,NX]   fp32
__device__ __nv_bfloat16 g_xhi[B_ * S_ * NX_];
__device__ __nv_bfloat16 g_xlo[B_ * S_ * NX_];
__device__ __nv_bfloat16 g_ahi[B_ * S_ * NX_];
__device__ __nv_bfloat16 g_alo[B_ * S_ * NX_];
__device__ __nv_bfloat16 g_wqkv_hi[3 * NX_ * NX_];   // [N=3072, K=1024] (transposed)
__device__ __nv_bfloat16 g_wqkv_lo[3 * NX_ * NX_];
__device__ __nv_bfloat16 g_wproj_hi[NX_ * NX_];      // [N=1024, K=1024]
__device__ __nv_bfloat16 g_wproj_lo[NX_ * NX_];

// ---------------- PTX helpers (baseline ISA only: sm_80-era ops) -------------
__device__ __forceinline__ uint32_t smem_to_u32(const void* p) {
    uint32_t a;
    asm("{ .reg .u64 t; cvta.to.shared.u64 t, %1; cvt.u32.u64 %0, t; }"
        : "=r"(a) : "l"(p));
    return a;
}
__device__ __forceinline__ void cp_async16(uint32_t dst, const void* src) {
    asm volatile("cp.async.cg.shared.global [%0], [%1], 16;"
                 :: "r"(dst), "l"(src) : "memory");
}
#define CP_COMMIT() asm volatile("cp.async.commit_group;" ::: "memory")
#define CP_WAIT(n)  asm volatile("cp.async.wait_group %0;" :: "n"(n) : "memory")

__device__ __forceinline__ void ldsm_x4(uint32_t& r0, uint32_t& r1,
                                        uint32_t& r2, uint32_t& r3, uint32_t addr) {
    asm volatile("ldmatrix.sync.aligned.m8n8.x4.shared.b16 {%0,%1,%2,%3}, [%4];"
                 : "=r"(r0), "=r"(r1), "=r"(r2), "=r"(r3) : "r"(addr));
}
__device__ __forceinline__ void mma16816(float* c, const uint32_t* a, const uint32_t* b) {
    asm volatile("mma.sync.aligned.m16n8k16.row.col.f32.bf16.bf16.f32 "
                 "{%0,%1,%2,%3}, {%4,%5,%6,%7}, {%8,%9}, {%0,%1,%2,%3};"
                 : "+f"(c[0]), "+f"(c[1]), "+f"(c[2]), "+f"(c[3])
                 : "r"(a[0]), "r"(a[1]), "r"(a[2]), "r"(a[3]),
                   "r"(b[0]), "r"(b[1]));
}
__device__ __forceinline__ void split32(float v, __nv_bfloat16& h, __nv_bfloat16& l) {
    h = __float2bfloat16(v);
    l = __float2bfloat16(v - __bfloat162float(h));
}

// ---------------------------------------------------------------------------
// split: fp32 -> (hi, lo) bf16, same layout. n4 = n/4.
// ---------------------------------------------------------------------------
__global__ void split_kernel(const float* __restrict__ in,
                             __nv_bfloat16* __restrict__ hi,
                             __nv_bfloat16* __restrict__ lo, int n4)
{
    int i = blockIdx.x * blockDim.x + threadIdx.x;
    if (i >= n4) return;
    float4 v = ((const float4*)in)[i];
    __nv_bfloat16 h0, h1, h2, h3, l0, l1, l2, l3;
    split32(v.x, h0, l0); split32(v.y, h1, l1);
    split32(v.z, h2, l2); split32(v.w, h3, l3);
    ((__nv_bfloat162*)hi)[2 * i]     = __nv_bfloat162(h0, h1);
    ((__nv_bfloat162*)hi)[2 * i + 1] = __nv_bfloat162(h2, h3);
    ((__nv_bfloat162*)lo)[2 * i]     = __nv_bfloat162(l0, l1);
    ((__nv_bfloat162*)lo)[2 * i + 1] = __nv_bfloat162(l2, l3);
}

// ---------------------------------------------------------------------------
// transpose + split: W[K,N] fp32 -> T_hi/T_lo [N,K] bf16
// ---------------------------------------------------------------------------
__global__ void tsplit_kernel(const float* __restrict__ W,
                              __nv_bfloat16* __restrict__ Thi,
                              __nv_bfloat16* __restrict__ Tlo, int K, int N)
{
    __shared__ float t[32][33];
    int n0 = blockIdx.x * 32, k0 = blockIdx.y * 32;
    int tx = threadIdx.x, ty = threadIdx.y;  // 32 x 8
#pragma unroll
    for (int i = 0; i < 4; i++)
        t[ty + i * 8][tx] = W[(long)(k0 + ty + i * 8) * N + n0 + tx];
    __syncthreads();
#pragma unroll
    for (int i = 0; i < 4; i++) {
        float v = t[tx][ty + i * 8];
        __nv_bfloat16 h, l;
        split32(v, h, l);
        long o = (long)(n0 + ty + i * 8) * K + k0 + tx;
        Thi[o] = h;
        Tlo[o] = l;
    }
}

// ---------------------------------------------------------------------------
// bf16-split GEMM on mma.sync (HMMA) — unchanged from R5 (best: 42% tensor).
// ---------------------------------------------------------------------------
#define ROWB    80
#define TILE_B  (128 * ROWB)
#define STAGE_B (4 * TILE_B)
#define NSTAGE  2
#define GEMM_SMEM_DYN (NSTAGE * STAGE_B)

__global__ void __launch_bounds__(256, 2) gemm_mma(
    const __nv_bfloat16* __restrict__ Ahi, const __nv_bfloat16* __restrict__ Alo,
    const __nv_bfloat16* __restrict__ Bhi, const __nv_bfloat16* __restrict__ Blo,
    const float* __restrict__ bias, float* __restrict__ C,
    int M, int N, int K)
{
    extern __shared__ __align__(128) char smem[];
    const uint32_t sbase = smem_to_u32(smem);

    const int tid  = threadIdx.x;
    const int lane = tid & 31;
    const int wid  = tid >> 5;
    const int wm   = wid & 1;
    const int wn   = wid >> 1;
    const int bm   = blockIdx.y * 128;
    const int bn   = blockIdx.x * 128;

    float acc[4][4][4];
#pragma unroll
    for (int mi = 0; mi < 4; mi++)
#pragma unroll
        for (int ni = 0; ni < 4; ni++)
#pragma unroll
            for (int r = 0; r < 4; r++) acc[mi][ni][r] = 0.f;

    const int row = tid & 127;
    const int ch  = tid >> 7;

    const __nv_bfloat16* gA[2] = { Ahi + (long)bm * K, Alo + (long)bm * K };
    const __nv_bfloat16* gB[2] = { Bhi + (long)bn * K, Blo + (long)bn * K };

    const int NS = K / 32;

    auto load_stage = [&](int s) {
        const int k0 = s * 32;
        const uint32_t buf = sbase + (s & 1) * STAGE_B;
#pragma unroll
        for (int t = 0; t < 2; t++) {
#pragma unroll
            for (int j = 0; j < 2; j++) {
                int c = ch + 2 * j;
                cp_async16(buf + t * TILE_B + row * ROWB + c * 16,
                           gA[t] + (long)row * K + k0 + c * 8);
                cp_async16(buf + (2 + t) * TILE_B + row * ROWB + c * 16,
                           gB[t] + (long)row * K + k0 + c * 8);
            }
        }
    };

    load_stage(0);
    CP_COMMIT();

    const int arow  = wm * 64 + (lane & 15);
    const int asel  = (lane >> 4) << 3;
    const int brow  = wn * 32 + (lane & 7) + ((lane >> 4) << 3);
    const int bsel  = ((lane >> 3) & 1) << 3;

    for (int s = 0; s < NS; s++) {
        if (s + 1 < NS) {
            load_stage(s + 1);
            CP_COMMIT();
            CP_WAIT(1);
        } else {
            CP_WAIT(0);
        }
        __syncthreads();

        const uint32_t buf = sbase + (s & 1) * STAGE_B;
#pragma unroll
        for (int ks = 0; ks < 2; ks++) {
            uint32_t a[4][4];
            uint32_t b[2][4][2];
            const int acol = ks * 16 + asel;
            const int bcol = ks * 16 + bsel;
#pragma unroll
            for (int t = 0; t < 2; t++)
#pragma unroll
                for (int nj = 0; nj < 2; nj++)
                    ldsm_x4(b[t][nj * 2][0], b[t][nj * 2][1],
                            b[t][nj * 2 + 1][0], b[t][nj * 2 + 1][1],
                            buf + (2 + t) * TILE_B + (brow + nj * 16) * ROWB + bcol * 2);

#pragma unroll
            for (int mi = 0; mi < 4; mi++)
                ldsm_x4(a[mi][0], a[mi][1], a[mi][2], a[mi][3],
                        buf + 0 * TILE_B + (arow + mi * 16) * ROWB + acol * 2);
#pragma unroll
            for (int mi = 0; mi < 4; mi++)
#pragma unroll
                for (int ni = 0; ni < 4; ni++)
                    mma16816(acc[mi][ni], a[mi], b[0][ni]);
#pragma unroll
            for (int mi = 0; mi < 4; mi++)
#pragma unroll
                for (int ni = 0; ni < 4; ni++)
                    mma16816(acc[mi][ni], a[mi], b[1][ni]);

#pragma unroll
            for (int mi = 0; mi < 4; mi++)
                ldsm_x4(a[mi][0], a[mi][1], a[mi][2], a[mi][3],
                        buf + 1 * TILE_B + (arow + mi * 16) * ROWB + acol * 2);
#pragma unroll
            for (int mi = 0; mi < 4; mi++)
#pragma unroll
                for (int ni = 0; ni < 4; ni++)
                    mma16816(acc[mi][ni], a[mi], b[0][ni]);
        }
        __syncthreads();
    }

    const int g  = lane >> 2;
    const int t4 = lane & 3;
#pragma unroll
    for (int mi = 0; mi < 4; mi++) {
#pragma unroll
        for (int ni = 0; ni < 4; ni++) {
            const int col = bn + wn * 32 + ni * 8 + t4 * 2;
            const long r0 = bm + wm * 64 + mi * 16 + g;
            float2 bb = *(const float2*)&bias[col];
            float2 o0 = { acc[mi][ni][0] + bb.x, acc[mi][ni][1] + bb.y };
            float2 o1 = { acc[mi][ni][2] + bb.x, acc[mi][ni][3] + bb.y };
            *(float2*)&C[r0 * N + col] = o0;
            *(float2*)&C[(r0 + 8) * N + col] = o1;
        }
    }
}

// ---------------------------------------------------------------------------
// Causal flash-attention with split-bf16 HMMA for Q@K^T and P@V.
// One CTA per (b, h, 64-row q tile). 256 threads = 8 warps (4 along M, 2 along N).
// ---------------------------------------------------------------------------
#define ATS 72    // bf16 tile row stride (144B: 16B-aligned rows, conflict-free ldsm)
#define SST 68    // fp32 S row stride

#define Q_HI   0
#define Q_LO   (64 * ATS)
#define K_HI   (2 * 64 * ATS)
#define K_LO   (3 * 64 * ATS)
#define VT_HI  (4 * 64 * ATS)
#define VT_LO  (5 * 64 * ATS)
#define P_HI   (6 * 64 * ATS)
#define P_LO   (7 * 64 * ATS)
#define S_OFF  (8 * 64 * ATS)                 // in bf16 units; cast region to float
#define ATTN2_SMEM (8 * 64 * ATS * 2 + 64 * SST * 4 + 2 * 64 * 4)

__global__ void __launch_bounds__(256, 2) attn_mma(
    const float* __restrict__ qkv, float* __restrict__ out)
{
    extern __shared__ __align__(128) char asmem[];
    __nv_bfloat16* bfs = (__nv_bfloat16*)asmem;
    float* Ss      = (float*)(asmem + S_OFF * 2);
    float* alpha_s = Ss + 64 * SST;
    float* linv_s  = alpha_s + 64;
    const uint32_t sb = smem_to_u32(asmem);

    const int tid  = threadIdx.x;
    const int lane = tid & 31;
    const int wid  = tid >> 5;
    const int wm   = wid & 3;            // 4 warps along q-rows (16 each)
    const int wn   = wid >> 2;           // 2 warps along cols (32 each)
    const int qt   = blockIdx.x;
    const int h    = blockIdx.y;
    const int b    = blockIdx.z;
    const int q0   = qt * 64;
    const int tx   = tid & 15;
    const int ty   = tid >> 4;

    const long base = (long)b * S_ * (3 * NX_);

    // ---- load Q tile, scaled, split
#pragma unroll
    for (int i = 0; i < 16; i++) {
        int idx = tid + i * 256;
        int r = idx >> 6, d = idx & 63;
        float v = qkv[base + (long)(q0 + r) * (3 * NX_) + h * D_ + d] * 0.125f;
        __nv_bfloat16 hh, ll;
        split32(v, hh, ll);
        bfs[Q_HI + r * ATS + d] = hh;
        bfs[Q_LO + r * ATS + d] = ll;
    }

    float m[4], l[4];
    float oacc[4][4];
#pragma unroll
    for (int i = 0; i < 4; i++) {
        m[i] = -1e30f; l[i] = 0.f;
#pragma unroll
        for (int j = 0; j < 4; j++) oacc[i][j] = 0.f;
    }

    // fragment addressing (same pattern as gemm_mma)
    const int arow = wm * 16 + (lane & 15);
    const int asel = (lane >> 4) << 3;
    const int brow = wn * 32 + (lane & 7) + ((lane >> 4) << 3);
    const int bsel = ((lane >> 3) & 1) << 3;
    const int g    = lane >> 2;
    const int t4   = lane & 3;

    for (int kt = 0; kt <= qt; kt++) {
        __syncthreads();   // smem reuse guard (K/V/P from previous iter; Q on iter 0)

        // ---- load K tile split
#pragma unroll
        for (int i = 0; i < 16; i++) {
            int idx = tid + i * 256;
            int r = idx >> 6, d = idx & 63;
            float v = qkv[base + (long)(kt * 64 + r) * (3 * NX_) + NX_ + h * D_ + d];
            __nv_bfloat16 hh, ll;
            split32(v, hh, ll);
            bfs[K_HI + r * ATS + d] = hh;
            bfs[K_LO + r * ATS + d] = ll;
        }
        // ---- load V tile transposed + split: Vt[d][k] = V[k][d]
        {
            int r  = tid >> 2;            // V row (seq) 0..63
            int dg = (tid & 3) * 16;      // 16 d per thread
            const float* vrow = qkv + base + (long)(kt * 64 + r) * (3 * NX_)
                                + 2 * NX_ + h * D_ + dg;
#pragma unroll
            for (int i = 0; i < 16; i++) {
                __nv_bfloat16 hh, ll;
                split32(vrow[i], hh, ll);
                bfs[VT_HI + (dg + i) * ATS + r] = hh;
                bfs[VT_LO + (dg + i) * ATS + r] = ll;
            }
        }
        __syncthreads();

        // ---- S = Q @ K^T (3-product split) ----
        float sacc[4][4];
#pragma unroll
        for (int ni = 0; ni < 4; ni++)
#pragma unroll
            for (int r = 0; r < 4; r++) sacc[ni][r] = 0.f;

#pragma unroll
        for (int ks = 0; ks < 4; ks++) {
            const int acol = ks * 16 + asel;
            const int bcol = ks * 16 + bsel;
            uint32_t ah[4], al[4], bh[4][2], bl[4][2];
            ldsm_x4(ah[0], ah[1], ah[2], ah[3],
                    sb + (Q_HI + arow * ATS + acol) * 2);
            ldsm_x4(al[0], al[1], al[2], al[3],
                    sb + (Q_LO + arow * ATS + acol) * 2);
#pragma unroll
            for (int nj = 0; nj < 2; nj++) {
                ldsm_x4(bh[nj * 2][0], bh[nj * 2][1], bh[nj * 2 + 1][0], bh[nj * 2 + 1][1],
                        sb + (K_HI + (brow + nj * 16) * ATS + bcol) * 2);
                ldsm_x4(bl[nj * 2][0], bl[nj * 2][1], bl[nj * 2 + 1][0], bl[nj * 2 + 1][1],
                        sb + (K_LO + (brow + nj * 16) * ATS + bcol) * 2);
            }
#pragma unroll
            for (int ni = 0; ni < 4; ni++) {
                mma16816(sacc[ni], ah, bh[ni]);
                mma16816(sacc[ni], ah, bl[ni]);
                mma16816(sacc[ni], al, bh[ni]);
            }
        }
        // store S fragments to smem fp32
#pragma unroll
        for (int ni = 0; ni < 4; ni++) {
            const int col = wn * 32 + ni * 8 + t4 * 2;
            *(float2*)&Ss[(wm * 16 + g) * SST + col]     = make_float2(sacc[ni][0], sacc[ni][1]);
            *(float2*)&Ss[(wm * 16 + g + 8) * SST + col] = make_float2(sacc[ni][2], sacc[ni][3]);
        }
        __syncthreads();

        // ---- scalar online softmax on smem S; emit Phi/Plo + alpha ----
        float s[4][4];
#pragma unroll
        for (int i = 0; i < 4; i++)
#pragma unroll
            for (int j = 0; j < 4; j++)
                s[i][j] = Ss[(ty * 4 + i) * SST + tx * 4 + j];

        if (kt == qt) {
#pragma unroll
            for (int i = 0; i < 4; i++)
#pragma unroll
                for (int j = 0; j < 4; j++)
                    if (tx * 4 + j > ty * 4 + i) s[i][j] = -1e9f;
        }

#pragma unroll
        for (int i = 0; i < 4; i++) {
            float mx = fmaxf(fmaxf(s[i][0], s[i][1]), fmaxf(s[i][2], s[i][3]));
#pragma unroll
            for (int off = 8; off > 0; off >>= 1)
                mx = fmaxf(mx, __shfl_xor_sync(0xffffffffu, mx, off));
            float mnew = fmaxf(m[i], mx);
            float alpha = __expf(m[i] - mnew);
            m[i] = mnew;
            float rs = 0.f;
#pragma unroll
            for (int j = 0; j < 4; j++) {
                s[i][j] = __expf(s[i][j] - mnew);
                rs += s[i][j];
            }
#pragma unroll
            for (int off = 8; off > 0; off >>= 1)
                rs += __shfl_xor_sync(0xffffffffu, rs, off);
            l[i] = l[i] * alpha + rs;
            if (tx == 0) alpha_s[ty * 4 + i] = alpha;
            const int pr = (ty * 4 + i) * ATS + tx * 4;
#pragma unroll
            for (int j = 0; j < 4; j += 2) {
                __nv_bfloat16 h0, l0, h1, l1;
                split32(s[i][j], h0, l0);
                split32(s[i][j + 1], h1, l1);
                *(__nv_bfloat162*)&bfs[P_HI + pr + j] = __nv_bfloat162(h0, h1);
                *(__nv_bfloat162*)&bfs[P_LO + pr + j] = __nv_bfloat162(l0, l1);
            }
        }
        __syncthreads();

        // ---- O = O*alpha + P @ V (3-product split) ----
        const float al0 = alpha_s[wm * 16 + g];
        const float al1 = alpha_s[wm * 16 + g + 8];
#pragma unroll
        for (int ni = 0; ni < 4; ni++) {
            oacc[ni][0] *= al0; oacc[ni][1] *= al0;
            oacc[ni][2] *= al1; oacc[ni][3] *= al1;
        }
#pragma unroll
        for (int ks = 0; ks < 4; ks++) {
            const int acol = ks * 16 + asel;
            const int bcol = ks * 16 + bsel;
            uint32_t ah[4], al[4], bh[4][2], bl[4][2];
            ldsm_x4(ah[0], ah[1], ah[2], ah[3],
                    sb + (P_HI + arow * ATS + acol) * 2);
            ldsm_x4(al[0], al[1], al[2], al[3],
                    sb + (P_LO + arow * ATS + acol) * 2);
#pragma unroll
            for (int nj = 0; nj < 2; nj++) {
                ldsm_x4(bh[nj * 2][0], bh[nj * 2][1], bh[nj * 2 + 1][0], bh[nj * 2 + 1][1],
                        sb + (VT_HI + (brow + nj * 16) * ATS + bcol) * 2);
                ldsm_x4(bl[nj * 2][0], bl[nj * 2][1], bl[nj * 2 + 1][0], bl[nj * 2 + 1][1],
                        sb + (VT_LO + (brow + nj * 16) * ATS + bcol) * 2);
            }
#pragma unroll
            for (int ni = 0; ni < 4; ni++) {
                mma16816(oacc[ni], ah, bh[ni]);
                mma16816(oacc[ni], ah, bl[ni]);
                mma16816(oacc[ni], al, bh[ni]);
            }
        }
    }

    // ---- epilogue: normalize and write
#pragma unroll
    for (int i = 0; i < 4; i++)
        if (tx == 0) linv_s[ty * 4 + i] = 1.f / l[i];
    __syncthreads();

    const float li0 = linv_s[wm * 16 + g];
    const float li1 = linv_s[wm * 16 + g + 8];
#pragma unroll
    for (int ni = 0; ni < 4; ni++) {
        const int col = h * D_ + wn * 32 + ni * 8 + t4 * 2;
        const long r0 = (long)b * S_ + q0 + wm * 16 + g;
        *(float2*)&out[r0 * NX_ + col] =
            make_float2(oacc[ni][0] * li0, oacc[ni][1] * li0);
        *(float2*)&out[(r0 + 8) * NX_ + col] =
            make_float2(oacc[ni][2] * li1, oacc[ni][3] * li1);
    }
}

// ---------------------------------------------------------------------------
extern "C" void kernel_launch(void* const* d_in, const int* in_sizes, int n_in,
                              void* d_out, int out_size)
{
    const float* x      = (const float*)d_in[0];
    const float* w_attn = (const float*)d_in[1];
    const float* b_attn = (const float*)d_in[2];
    const float* w_proj = (const float*)d_in[3];
    const float* b_proj = (const float*)d_in[4];
    float* out = (float*)d_out;

    float *qkv, *attn;
    __nv_bfloat16 *xhi, *xlo, *ahi, *alo, *wqh, *wql, *wph, *wpl;
    cudaGetSymbolAddress((void**)&qkv, g_qkv);
    cudaGetSymbolAddress((void**)&attn, g_attn);
    cudaGetSymbolAddress((void**)&xhi, g_xhi);
    cudaGetSymbolAddress((void**)&xlo, g_xlo);
    cudaGetSymbolAddress((void**)&ahi, g_ahi);
    cudaGetSymbolAddress((void**)&alo, g_alo);
    cudaGetSymbolAddress((void**)&wqh, g_wqkv_hi);
    cudaGetSymbolAddress((void**)&wql, g_wqkv_lo);
    cudaGetSymbolAddress((void**)&wph, g_wproj_hi);
    cudaGetSymbolAddress((void**)&wpl, g_wproj_lo);

    cudaFuncSetAttribute(attn_mma,
                         cudaFuncAttributeMaxDynamicSharedMemorySize,
                         ATTN2_SMEM);
    cudaFuncSetAttribute(gemm_mma,
                         cudaFuncAttributeMaxDynamicSharedMemorySize,
                         GEMM_SMEM_DYN);

    const int M = B_ * S_;  // 8192

    // split x
    {
        int n4 = M * NX_ / 4;
        split_kernel<<<(n4 + 255) / 256, 256>>>(x, xhi, xlo, n4);
    }
    // transpose+split weights
    tsplit_kernel<<<dim3(3 * NX_ / 32, NX_ / 32), dim3(32, 8)>>>(w_attn, wqh, wql, NX_, 3 * NX_);
    tsplit_kernel<<<dim3(NX_ / 32, NX_ / 32), dim3(32, 8)>>>(w_proj, wph, wpl, NX_, NX_);

    // QKV GEMM
    gemm_mma<<<dim3(3 * NX_ / 128, M / 128), 256, GEMM_SMEM_DYN>>>(
        xhi, xlo, wqh, wql, b_attn, qkv, M, 3 * NX_, NX_);

    // attention (HMMA)
    attn_mma<<<dim3(S_ / 64, H_, B_), 256, ATTN2_SMEM>>>(qkv, attn);

    // split attention output
    {
        int n4 = M * NX_ / 4;
        split_kernel<<<(n4 + 255) / 256, 256>>>(attn, ahi, alo, n4);
    }
    // projection GEMM
    gemm_mma<<<dim3(NX_ / 128, M / 128), 256, GEMM_SMEM_DYN>>>(
        ahi, alo, wph, wpl, b_proj, out, M, NX_, NX_);
}

// round 7
// speedup vs baseline: 2.0040x; 1.1501x over previous
#include <cuda_runtime.h>
#include <cuda_bf16.h>
#include <cstdint>

#define B_  8
#define S_  1024
#define NX_ 1024
#define H_  16
#define D_  64

// ---------------- scratch (__device__ globals; no allocation) ----------------
__device__ float g_qkv[B_ * S_ * 3 * NX_];           // [B,S,3*NX] fp32
__device__ float g_attn[B_ * S_ * NX_];              // [B,S,NX]   fp32
__device__ __nv_bfloat16 g_xhi[B_ * S_ * NX_];
__device__ __nv_bfloat16 g_xlo[B_ * S_ * NX_];
__device__ __nv_bfloat16 g_ahi[B_ * S_ * NX_];
__device__ __nv_bfloat16 g_alo[B_ * S_ * NX_];
__device__ __nv_bfloat16 g_wqkv_hi[3 * NX_ * NX_];   // [N=3072, K=1024]
__device__ __nv_bfloat16 g_wqkv_lo[3 * NX_ * NX_];
__device__ __nv_bfloat16 g_wproj_hi[NX_ * NX_];
__device__ __nv_bfloat16 g_wproj_lo[NX_ * NX_];
// pre-split attention operands
__device__ __nv_bfloat16 g_qhi[B_ * H_ * S_ * D_];   // [b,h,s,d], pre-scaled
__device__ __nv_bfloat16 g_qlo[B_ * H_ * S_ * D_];
__device__ __nv_bfloat16 g_khi[B_ * H_ * S_ * D_];   // [b,h,s,d]
__device__ __nv_bfloat16 g_klo[B_ * H_ * S_ * D_];
__device__ __nv_bfloat16 g_vthi[B_ * H_ * D_ * S_];  // [b,h,d,s] (transposed)
__device__ __nv_bfloat16 g_vtlo[B_ * H_ * D_ * S_];

// ---------------- PTX helpers (baseline ISA only: sm_80-era ops) -------------
__device__ __forceinline__ uint32_t smem_to_u32(const void* p) {
    uint32_t a;
    asm("{ .reg .u64 t; cvta.to.shared.u64 t, %1; cvt.u32.u64 %0, t; }"
        : "=r"(a) : "l"(p));
    return a;
}
__device__ __forceinline__ void cp_async16(uint32_t dst, const void* src) {
    asm volatile("cp.async.cg.shared.global [%0], [%1], 16;"
                 :: "r"(dst), "l"(src) : "memory");
}
#define CP_COMMIT() asm volatile("cp.async.commit_group;" ::: "memory")
#define CP_WAIT(n)  asm volatile("cp.async.wait_group %0;" :: "n"(n) : "memory")

__device__ __forceinline__ void ldsm_x4(uint32_t& r0, uint32_t& r1,
                                        uint32_t& r2, uint32_t& r3, uint32_t addr) {
    asm volatile("ldmatrix.sync.aligned.m8n8.x4.shared.b16 {%0,%1,%2,%3}, [%4];"
                 : "=r"(r0), "=r"(r1), "=r"(r2), "=r"(r3) : "r"(addr));
}
__device__ __forceinline__ void mma16816(float* c, const uint32_t* a, const uint32_t* b) {
    asm volatile("mma.sync.aligned.m16n8k16.row.col.f32.bf16.bf16.f32 "
                 "{%0,%1,%2,%3}, {%4,%5,%6,%7}, {%8,%9}, {%0,%1,%2,%3};"
                 : "+f"(c[0]), "+f"(c[1]), "+f"(c[2]), "+f"(c[3])
                 : "r"(a[0]), "r"(a[1]), "r"(a[2]), "r"(a[3]),
                   "r"(b[0]), "r"(b[1]));
}
__device__ __forceinline__ void split32(float v, __nv_bfloat16& h, __nv_bfloat16& l) {
    h = __float2bfloat16(v);
    l = __float2bfloat16(v - __bfloat162float(h));
}

// ---------------------------------------------------------------------------
// split: fp32 -> (hi, lo) bf16, same layout.
// ---------------------------------------------------------------------------
__global__ void split_kernel(const float* __restrict__ in,
                             __nv_bfloat16* __restrict__ hi,
                             __nv_bfloat16* __restrict__ lo, int n4)
{
    int i = blockIdx.x * blockDim.x + threadIdx.x;
    if (i >= n4) return;
    float4 v = ((const float4*)in)[i];
    __nv_bfloat16 h0, h1, h2, h3, l0, l1, l2, l3;
    split32(v.x, h0, l0); split32(v.y, h1, l1);
    split32(v.z, h2, l2); split32(v.w, h3, l3);
    ((__nv_bfloat162*)hi)[2 * i]     = __nv_bfloat162(h0, h1);
    ((__nv_bfloat162*)hi)[2 * i + 1] = __nv_bfloat162(h2, h3);
    ((__nv_bfloat162*)lo)[2 * i]     = __nv_bfloat162(l0, l1);
    ((__nv_bfloat162*)lo)[2 * i + 1] = __nv_bfloat162(l2, l3);
}

// ---------------------------------------------------------------------------
// transpose + split: W[K,N] fp32 -> T_hi/T_lo [N,K] bf16
// ---------------------------------------------------------------------------
__global__ void tsplit_kernel(const float* __restrict__ W,
                              __nv_bfloat16* __restrict__ Thi,
                              __nv_bfloat16* __restrict__ Tlo, int K, int N)
{
    __shared__ float t[32][33];
    int n0 = blockIdx.x * 32, k0 = blockIdx.y * 32;
    int tx = threadIdx.x, ty = threadIdx.y;  // 32 x 8
#pragma unroll
    for (int i = 0; i < 4; i++)
        t[ty + i * 8][tx] = W[(long)(k0 + ty + i * 8) * N + n0 + tx];
    __syncthreads();
#pragma unroll
    for (int i = 0; i < 4; i++) {
        float v = t[tx][ty + i * 8];
        __nv_bfloat16 h, l;
        split32(v, h, l);
        long o = (long)(n0 + ty + i * 8) * K + k0 + tx;
        Thi[o] = h;
        Tlo[o] = l;
    }
}

// ---------------------------------------------------------------------------
// qk_split: qkv fp32 [B,S,3NX] -> Q(scaled)/K bf16 hi/lo in [b,h,s,d]
// ---------------------------------------------------------------------------
__global__ void qk_split(const float* __restrict__ qkv,
                         __nv_bfloat16* __restrict__ Qhi, __nv_bfloat16* __restrict__ Qlo,
                         __nv_bfloat16* __restrict__ Khi, __nv_bfloat16* __restrict__ Klo)
{
    int idx = blockIdx.x * blockDim.x + threadIdx.x;   // over B*S*NX/4 = 2M
    if (idx >= B_ * S_ * NX_ / 4) return;
    int c4  = idx & 255;            // NX/4 = 256 column groups
    long row = idx >> 8;            // b*S + s
    int h = c4 >> 4, d4 = c4 & 15;
    int b = (int)(row >> 10), s = (int)(row & 1023);

    float4 q = ((const float4*)(qkv + row * 3072))[c4];
    float4 k = ((const float4*)(qkv + row * 3072 + 1024))[c4];
    q.x *= 0.125f; q.y *= 0.125f; q.z *= 0.125f; q.w *= 0.125f;

    long o = (((long)b * H_ + h) * S_ + s) * D_ + d4 * 4;
    __nv_bfloat16 h0, h1, h2, h3, l0, l1, l2, l3;
    split32(q.x, h0, l0); split32(q.y, h1, l1);
    split32(q.z, h2, l2); split32(q.w, h3, l3);
    *(__nv_bfloat162*)&Qhi[o]     = __nv_bfloat162(h0, h1);
    *(__nv_bfloat162*)&Qhi[o + 2] = __nv_bfloat162(h2, h3);
    *(__nv_bfloat162*)&Qlo[o]     = __nv_bfloat162(l0, l1);
    *(__nv_bfloat162*)&Qlo[o + 2] = __nv_bfloat162(l2, l3);
    split32(k.x, h0, l0); split32(k.y, h1, l1);
    split32(k.z, h2, l2); split32(k.w, h3, l3);
    *(__nv_bfloat162*)&Khi[o]     = __nv_bfloat162(h0, h1);
    *(__nv_bfloat162*)&Khi[o + 2] = __nv_bfloat162(h2, h3);
    *(__nv_bfloat162*)&Klo[o]     = __nv_bfloat162(l0, l1);
    *(__nv_bfloat162*)&Klo[o + 2] = __nv_bfloat162(l2, l3);
}

// ---------------------------------------------------------------------------
// vt_split: V from qkv -> VT bf16 hi/lo [b,h,d,s] (transposed), tiled 32x32
// ---------------------------------------------------------------------------
__global__ void vt_split(const float* __restrict__ qkv,
                         __nv_bfloat16* __restrict__ VThi,
                         __nv_bfloat16* __restrict__ VTlo)
{
    __shared__ float t[32][33];
    int bh = blockIdx.z;
    int b = bh >> 4, h = bh & 15;
    int s0 = blockIdx.x * 32, d0 = blockIdx.y * 32;
    int tx = threadIdx.x, ty = threadIdx.y;  // 32 x 8
    long base = (long)b * S_ * 3072 + 2048 + h * 64;
#pragma unroll
    for (int i = 0; i < 4; i++)
        t[ty + i * 8][tx] = qkv[base + (long)(s0 + ty + i * 8) * 3072 + d0 + tx];
    __syncthreads();
#pragma unroll
    for (int i = 0; i < 4; i++) {
        float v = t[tx][ty + i * 8];   // V[s0+tx][d0+ty+i*8]
        __nv_bfloat16 hh, ll;
        split32(v, hh, ll);
        long o = ((long)bh * D_ + d0 + ty + i * 8) * S_ + s0 + tx;
        VThi[o] = hh;
        VTlo[o] = ll;
    }
}

// ---------------------------------------------------------------------------
// bf16-split GEMM on mma.sync (HMMA) — unchanged from R5/R6.
// ---------------------------------------------------------------------------
#define ROWB    80
#define TILE_B  (128 * ROWB)
#define STAGE_B (4 * TILE_B)
#define GEMM_SMEM_DYN (2 * STAGE_B)

__global__ void __launch_bounds__(256, 2) gemm_mma(
    const __nv_bfloat16* __restrict__ Ahi, const __nv_bfloat16* __restrict__ Alo,
    const __nv_bfloat16* __restrict__ Bhi, const __nv_bfloat16* __restrict__ Blo,
    const float* __restrict__ bias, float* __restrict__ C,
    int M, int N, int K)
{
    extern __shared__ __align__(128) char smem[];
    const uint32_t sbase = smem_to_u32(smem);

    const int tid  = threadIdx.x;
    const int lane = tid & 31;
    const int wid  = tid >> 5;
    const int wm   = wid & 1;
    const int wn   = wid >> 1;
    const int bm   = blockIdx.y * 128;
    const int bn   = blockIdx.x * 128;

    float acc[4][4][4];
#pragma unroll
    for (int mi = 0; mi < 4; mi++)
#pragma unroll
        for (int ni = 0; ni < 4; ni++)
#pragma unroll
            for (int r = 0; r < 4; r++) acc[mi][ni][r] = 0.f;

    const int row = tid & 127;
    const int ch  = tid >> 7;

    const __nv_bfloat16* gA[2] = { Ahi + (long)bm * K, Alo + (long)bm * K };
    const __nv_bfloat16* gB[2] = { Bhi + (long)bn * K, Blo + (long)bn * K };

    const int NS = K / 32;

    auto load_stage = [&](int s) {
        const int k0 = s * 32;
        const uint32_t buf = sbase + (s & 1) * STAGE_B;
#pragma unroll
        for (int t = 0; t < 2; t++) {
#pragma unroll
            for (int j = 0; j < 2; j++) {
                int c = ch + 2 * j;
                cp_async16(buf + t * TILE_B + row * ROWB + c * 16,
                           gA[t] + (long)row * K + k0 + c * 8);
                cp_async16(buf + (2 + t) * TILE_B + row * ROWB + c * 16,
                           gB[t] + (long)row * K + k0 + c * 8);
            }
        }
    };

    load_stage(0);
    CP_COMMIT();

    const int arow  = wm * 64 + (lane & 15);
    const int asel  = (lane >> 4) << 3;
    const int brow  = wn * 32 + (lane & 7) + ((lane >> 4) << 3);
    const int bsel  = ((lane >> 3) & 1) << 3;

    for (int s = 0; s < NS; s++) {
        if (s + 1 < NS) {
            load_stage(s + 1);
            CP_COMMIT();
            CP_WAIT(1);
        } else {
            CP_WAIT(0);
        }
        __syncthreads();

        const uint32_t buf = sbase + (s & 1) * STAGE_B;
#pragma unroll
        for (int ks = 0; ks < 2; ks++) {
            uint32_t a[4][4];
            uint32_t b[2][4][2];
            const int acol = ks * 16 + asel;
            const int bcol = ks * 16 + bsel;
#pragma unroll
            for (int t = 0; t < 2; t++)
#pragma unroll
                for (int nj = 0; nj < 2; nj++)
                    ldsm_x4(b[t][nj * 2][0], b[t][nj * 2][1],
                            b[t][nj * 2 + 1][0], b[t][nj * 2 + 1][1],
                            buf + (2 + t) * TILE_B + (brow + nj * 16) * ROWB + bcol * 2);

#pragma unroll
            for (int mi = 0; mi < 4; mi++)
                ldsm_x4(a[mi][0], a[mi][1], a[mi][2], a[mi][3],
                        buf + 0 * TILE_B + (arow + mi * 16) * ROWB + acol * 2);
#pragma unroll
            for (int mi = 0; mi < 4; mi++)
#pragma unroll
                for (int ni = 0; ni < 4; ni++)
                    mma16816(acc[mi][ni], a[mi], b[0][ni]);
#pragma unroll
            for (int mi = 0; mi < 4; mi++)
#pragma unroll
                for (int ni = 0; ni < 4; ni++)
                    mma16816(acc[mi][ni], a[mi], b[1][ni]);

#pragma unroll
            for (int mi = 0; mi < 4; mi++)
                ldsm_x4(a[mi][0], a[mi][1], a[mi][2], a[mi][3],
                        buf + 1 * TILE_B + (arow + mi * 16) * ROWB + acol * 2);
#pragma unroll
            for (int mi = 0; mi < 4; mi++)
#pragma unroll
                for (int ni = 0; ni < 4; ni++)
                    mma16816(acc[mi][ni], a[mi], b[0][ni]);
        }
        __syncthreads();
    }

    const int g  = lane >> 2;
    const int t4 = lane & 3;
#pragma unroll
    for (int mi = 0; mi < 4; mi++) {
#pragma unroll
        for (int ni = 0; ni < 4; ni++) {
            const int col = bn + wn * 32 + ni * 8 + t4 * 2;
            const long r0 = bm + wm * 64 + mi * 16 + g;
            float2 bb = *(const float2*)&bias[col];
            float2 o0 = { acc[mi][ni][0] + bb.x, acc[mi][ni][1] + bb.y };
            float2 o1 = { acc[mi][ni][2] + bb.x, acc[mi][ni][3] + bb.y };
            *(float2*)&C[r0 * N + col] = o0;
            *(float2*)&C[(r0 + 8) * N + col] = o1;
        }
    }
}

// ---------------------------------------------------------------------------
// Causal flash-attention, HMMA, all operands pre-split bf16 loaded via cp.async
// ---------------------------------------------------------------------------
#define ATS 72    // bf16 row stride (144B)
#define SST 68    // fp32 S row stride

#define Q_HI   0
#define Q_LO   (64 * ATS)
#define K_HI   (2 * 64 * ATS)
#define K_LO   (3 * 64 * ATS)
#define VT_HI  (4 * 64 * ATS)
#define VT_LO  (5 * 64 * ATS)
#define P_HI   (6 * 64 * ATS)
#define P_LO   (7 * 64 * ATS)
#define S_OFF  (8 * 64 * ATS)
#define ATTN2_SMEM (8 * 64 * ATS * 2 + 64 * SST * 4 + 2 * 64 * 4)

__global__ void __launch_bounds__(256, 2) attn_mma(
    const __nv_bfloat16* __restrict__ Qhi, const __nv_bfloat16* __restrict__ Qlo,
    const __nv_bfloat16* __restrict__ Khi, const __nv_bfloat16* __restrict__ Klo,
    const __nv_bfloat16* __restrict__ VThi, const __nv_bfloat16* __restrict__ VTlo,
    float* __restrict__ out)
{
    extern __shared__ __align__(128) char asmem[];
    __nv_bfloat16* bfs = (__nv_bfloat16*)asmem;
    float* Ss      = (float*)(asmem + S_OFF * 2);
    float* alpha_s = Ss + 64 * SST;
    float* linv_s  = alpha_s + 64;
    const uint32_t sb = smem_to_u32(asmem);

    const int tid  = threadIdx.x;
    const int lane = tid & 31;
    const int wid  = tid >> 5;
    const int wm   = wid & 3;
    const int wn   = wid >> 2;
    const int qt   = blockIdx.x;
    const int h    = blockIdx.y;
    const int b    = blockIdx.z;
    const int q0   = qt * 64;
    const int tx   = tid & 15;
    const int ty   = tid >> 4;

    const long bh = (long)b * H_ + h;

    // ---- Q tile via cp.async (once): 2 tiles x 64 rows x 8 chunks
    {
        const __nv_bfloat16* qs[2] = { Qhi + (bh * S_ + q0) * D_,
                                       Qlo + (bh * S_ + q0) * D_ };
#pragma unroll
        for (int j = 0; j < 4; j++) {
            int lin = tid + j * 256;          // 0..1023
            int t = lin >> 9;                 // 0..1
            int r = (lin >> 3) & 63, c = lin & 7;
            cp_async16(sb + (t ? Q_LO : Q_HI) * 2 + r * (ATS * 2) + c * 16,
                       qs[t] + (long)r * D_ + c * 8);
        }
    }

    float m[4], l[4];
    float oacc[4][4];
#pragma unroll
    for (int i = 0; i < 4; i++) {
        m[i] = -1e30f; l[i] = 0.f;
#pragma unroll
        for (int j = 0; j < 4; j++) oacc[i][j] = 0.f;
    }

    const int arow = wm * 16 + (lane & 15);
    const int asel = (lane >> 4) << 3;
    const int brow = wn * 32 + (lane & 7) + ((lane >> 4) << 3);
    const int bsel = ((lane >> 3) & 1) << 3;
    const int g    = lane >> 2;
    const int t4   = lane & 3;

    for (int kt = 0; kt <= qt; kt++) {
        __syncthreads();   // smem reuse guard

        // ---- K + VT tiles via cp.async: 4 tiles x 512 chunks
        {
            const __nv_bfloat16* srcs[4] = {
                Khi + (bh * S_ + kt * 64) * D_, Klo + (bh * S_ + kt * 64) * D_,
                VThi + bh * D_ * S_ + kt * 64,  VTlo + bh * D_ * S_ + kt * 64 };
            const long rstr[4]  = { D_, D_, S_, S_ };
            const uint32_t dof[4] = { K_HI, K_LO, VT_HI, VT_LO };
#pragma unroll
            for (int j = 0; j < 8; j++) {
                int t = j >> 1;
                int lin = tid + (j & 1) * 256;   // 0..511 within tile
                int r = lin >> 3, c = lin & 7;
                cp_async16(sb + dof[t] * 2 + r * (ATS * 2) + c * 16,
                           srcs[t] + (long)r * rstr[t] + c * 8);
            }
        }
        CP_COMMIT();
        CP_WAIT(0);
        __syncthreads();

        // ---- S = Q @ K^T (3-product split) ----
        float sacc[4][4];
#pragma unroll
        for (int ni = 0; ni < 4; ni++)
#pragma unroll
            for (int r = 0; r < 4; r++) sacc[ni][r] = 0.f;

#pragma unroll
        for (int ks = 0; ks < 4; ks++) {
            const int acol = ks * 16 + asel;
            const int bcol = ks * 16 + bsel;
            uint32_t ah[4], al[4], bh4[4][2], bl4[4][2];
            ldsm_x4(ah[0], ah[1], ah[2], ah[3],
                    sb + (Q_HI + arow * ATS + acol) * 2);
            ldsm_x4(al[0], al[1], al[2], al[3],
                    sb + (Q_LO + arow * ATS + acol) * 2);
#pragma unroll
            for (int nj = 0; nj < 2; nj++) {
                ldsm_x4(bh4[nj * 2][0], bh4[nj * 2][1], bh4[nj * 2 + 1][0], bh4[nj * 2 + 1][1],
                        sb + (K_HI + (brow + nj * 16) * ATS + bcol) * 2);
                ldsm_x4(bl4[nj * 2][0], bl4[nj * 2][1], bl4[nj * 2 + 1][0], bl4[nj * 2 + 1][1],
                        sb + (K_LO + (brow + nj * 16) * ATS + bcol) * 2);
            }
#pragma unroll
            for (int ni = 0; ni < 4; ni++) {
                mma16816(sacc[ni], ah, bh4[ni]);
                mma16816(sacc[ni], ah, bl4[ni]);
                mma16816(sacc[ni], al, bh4[ni]);
            }
        }
#pragma unroll
        for (int ni = 0; ni < 4; ni++) {
            const int col = wn * 32 + ni * 8 + t4 * 2;
            *(float2*)&Ss[(wm * 16 + g) * SST + col]     = make_float2(sacc[ni][0], sacc[ni][1]);
            *(float2*)&Ss[(wm * 16 + g + 8) * SST + col] = make_float2(sacc[ni][2], sacc[ni][3]);
        }
        __syncthreads();

        // ---- scalar online softmax; emit Phi/Plo + alpha ----
        float s[4][4];
#pragma unroll
        for (int i = 0; i < 4; i++)
#pragma unroll
            for (int j = 0; j < 4; j++)
                s[i][j] = Ss[(ty * 4 + i) * SST + tx * 4 + j];

        if (kt == qt) {
#pragma unroll
            for (int i = 0; i < 4; i++)
#pragma unroll
                for (int j = 0; j < 4; j++)
                    if (tx * 4 + j > ty * 4 + i) s[i][j] = -1e9f;
        }

#pragma unroll
        for (int i = 0; i < 4; i++) {
            float mx = fmaxf(fmaxf(s[i][0], s[i][1]), fmaxf(s[i][2], s[i][3]));
#pragma unroll
            for (int off = 8; off > 0; off >>= 1)
                mx = fmaxf(mx, __shfl_xor_sync(0xffffffffu, mx, off));
            float mnew = fmaxf(m[i], mx);
            float alpha = __expf(m[i] - mnew);
            m[i] = mnew;
            float rs = 0.f;
#pragma unroll
            for (int j = 0; j < 4; j++) {
                s[i][j] = __expf(s[i][j] - mnew);
                rs += s[i][j];
            }
#pragma unroll
            for (int off = 8; off > 0; off >>= 1)
                rs += __shfl_xor_sync(0xffffffffu, rs, off);
            l[i] = l[i] * alpha + rs;
            if (tx == 0) alpha_s[ty * 4 + i] = alpha;
            const int pr = (ty * 4 + i) * ATS + tx * 4;
#pragma unroll
            for (int j = 0; j < 4; j += 2) {
                __nv_bfloat16 h0, l0, h1, l1;
                split32(s[i][j], h0, l0);
                split32(s[i][j + 1], h1, l1);
                *(__nv_bfloat162*)&bfs[P_HI + pr + j] = __nv_bfloat162(h0, h1);
                *(__nv_bfloat162*)&bfs[P_LO + pr + j] = __nv_bfloat162(l0, l1);
            }
        }
        __syncthreads();

        // ---- O = O*alpha + P @ V ----
        const float al0 = alpha_s[wm * 16 + g];
        const float al1 = alpha_s[wm * 16 + g + 8];
#pragma unroll
        for (int ni = 0; ni < 4; ni++) {
            oacc[ni][0] *= al0; oacc[ni][1] *= al0;
            oacc[ni][2] *= al1; oacc[ni][3] *= al1;
        }
#pragma unroll
        for (int ks = 0; ks < 4; ks++) {
            const int acol = ks * 16 + asel;
            const int bcol = ks * 16 + bsel;
            uint32_t ah[4], al[4], bh4[4][2], bl4[4][2];
            ldsm_x4(ah[0], ah[1], ah[2], ah[3],
                    sb + (P_HI + arow * ATS + acol) * 2);
            ldsm_x4(al[0], al[1], al[2], al[3],
                    sb + (P_LO + arow * ATS + acol) * 2);
#pragma unroll
            for (int nj = 0; nj < 2; nj++) {
                ldsm_x4(bh4[nj * 2][0], bh4[nj * 2][1], bh4[nj * 2 + 1][0], bh4[nj * 2 + 1][1],
                        sb + (VT_HI + (brow + nj * 16) * ATS + bcol) * 2);
                ldsm_x4(bl4[nj * 2][0], bl4[nj * 2][1], bl4[nj * 2 + 1][0], bl4[nj * 2 + 1][1],
                        sb + (VT_LO + (brow + nj * 16) * ATS + bcol) * 2);
            }
#pragma unroll
            for (int ni = 0; ni < 4; ni++) {
                mma16816(oacc[ni], ah, bh4[ni]);
                mma16816(oacc[ni], ah, bl4[ni]);
                mma16816(oacc[ni], al, bh4[ni]);
            }
        }
    }

    // ---- epilogue
#pragma unroll
    for (int i = 0; i < 4; i++)
        if (tx == 0) linv_s[ty * 4 + i] = 1.f / l[i];
    __syncthreads();

    const float li0 = linv_s[wm * 16 + g];
    const float li1 = linv_s[wm * 16 + g + 8];
#pragma unroll
    for (int ni = 0; ni < 4; ni++) {
        const int col = h * D_ + wn * 32 + ni * 8 + t4 * 2;
        const long r0 = (long)b * S_ + q0 + wm * 16 + g;
        *(float2*)&out[r0 * NX_ + col] =
            make_float2(oacc[ni][0] * li0, oacc[ni][1] * li0);
        *(float2*)&out[(r0 + 8) * NX_ + col] =
            make_float2(oacc[ni][2] * li1, oacc[ni][3] * li1);
    }
}

// ---------------------------------------------------------------------------
extern "C" void kernel_launch(void* const* d_in, const int* in_sizes, int n_in,
                              void* d_out, int out_size)
{
    const float* x      = (const float*)d_in[0];
    const float* w_attn = (const float*)d_in[1];
    const float* b_attn = (const float*)d_in[2];
    const float* w_proj = (const float*)d_in[3];
    const float* b_proj = (const float*)d_in[4];
    float* out = (float*)d_out;

    float *qkv, *attn;
    __nv_bfloat16 *xhi, *xlo, *ahi, *alo, *wqh, *wql, *wph, *wpl;
    __nv_bfloat16 *qhi, *qlo, *khi, *klo, *vthi, *vtlo;
    cudaGetSymbolAddress((void**)&qkv, g_qkv);
    cudaGetSymbolAddress((void**)&attn, g_attn);
    cudaGetSymbolAddress((void**)&xhi, g_xhi);
    cudaGetSymbolAddress((void**)&xlo, g_xlo);
    cudaGetSymbolAddress((void**)&ahi, g_ahi);
    cudaGetSymbolAddress((void**)&alo, g_alo);
    cudaGetSymbolAddress((void**)&wqh, g_wqkv_hi);
    cudaGetSymbolAddress((void**)&wql, g_wqkv_lo);
    cudaGetSymbolAddress((void**)&wph, g_wproj_hi);
    cudaGetSymbolAddress((void**)&wpl, g_wproj_lo);
    cudaGetSymbolAddress((void**)&qhi, g_qhi);
    cudaGetSymbolAddress((void**)&qlo, g_qlo);
    cudaGetSymbolAddress((void**)&khi, g_khi);
    cudaGetSymbolAddress((void**)&klo, g_klo);
    cudaGetSymbolAddress((void**)&vthi, g_vthi);
    cudaGetSymbolAddress((void**)&vtlo, g_vtlo);

    cudaFuncSetAttribute(attn_mma,
                         cudaFuncAttributeMaxDynamicSharedMemorySize,
                         ATTN2_SMEM);
    cudaFuncSetAttribute(gemm_mma,
                         cudaFuncAttributeMaxDynamicSharedMemorySize,
                         GEMM_SMEM_DYN);

    const int M = B_ * S_;  // 8192

    // split x
    {
        int n4 = M * NX_ / 4;
        split_kernel<<<(n4 + 255) / 256, 256>>>(x, xhi, xlo, n4);
    }
    // transpose+split weights
    tsplit_kernel<<<dim3(3 * NX_ / 32, NX_ / 32), dim3(32, 8)>>>(w_attn, wqh, wql, NX_, 3 * NX_);
    tsplit_kernel<<<dim3(NX_ / 32, NX_ / 32), dim3(32, 8)>>>(w_proj, wph, wpl, NX_, NX_);

    // QKV GEMM
    gemm_mma<<<dim3(3 * NX_ / 128, M / 128), 256, GEMM_SMEM_DYN>>>(
        xhi, xlo, wqh, wql, b_attn, qkv, M, 3 * NX_, NX_);

    // pre-split attention operands
    qk_split<<<(M * NX_ / 4 + 255) / 256, 256>>>(qkv, qhi, qlo, khi, klo);
    vt_split<<<dim3(S_ / 32, D_ / 32, B_ * H_), dim3(32, 8)>>>(qkv, vthi, vtlo);

    // attention (HMMA, preconverted operands)
    attn_mma<<<dim3(S_ / 64, H_, B_), 256, ATTN2_SMEM>>>(
        qhi, qlo, khi, klo, vthi, vtlo, attn);

    // split attention output
    {
        int n4 = M * NX_ / 4;
        split_kernel<<<(n4 + 255) / 256, 256>>>(attn, ahi, alo, n4);
    }
    // projection GEMM
    gemm_mma<<<dim3(NX_ / 128, M / 128), 256, GEMM_SMEM_DYN>>>(
        ahi, alo, wph, wpl, b_proj, out, M, NX_, NX_);
}

// round 8
// speedup vs baseline: 2.5104x; 1.2527x over previous
#include <cuda_runtime.h>
#include <cuda_bf16.h>
#include <cuda_fp16.h>
#include <cstdint>

#define B_  8
#define S_  1024
#define NX_ 1024
#define H_  16
#define D_  64

// ---------------- scratch (__device__ globals; no allocation) ----------------
__device__ float g_qkv[B_ * S_ * 3 * NX_];           // [B,S,3*NX] fp32
__device__ float g_attn[B_ * S_ * NX_];              // [B,S,NX]   fp32
__device__ __half g_xhi[B_ * S_ * NX_];
__device__ __half g_xlo[B_ * S_ * NX_];
__device__ __half g_ahi[B_ * S_ * NX_];
__device__ __half g_alo[B_ * S_ * NX_];
__device__ __half g_wqkv_h[3 * NX_ * NX_];           // [N=3072, K=1024] fp16 trunc
__device__ __half g_wproj_h[NX_ * NX_];              // [N=1024, K=1024]
// pre-split attention operands (bf16, 3-product path — unchanged)
__device__ __nv_bfloat16 g_qhi[B_ * H_ * S_ * D_];
__device__ __nv_bfloat16 g_qlo[B_ * H_ * S_ * D_];
__device__ __nv_bfloat16 g_khi[B_ * H_ * S_ * D_];
__device__ __nv_bfloat16 g_klo[B_ * H_ * S_ * D_];
__device__ __nv_bfloat16 g_vthi[B_ * H_ * D_ * S_];
__device__ __nv_bfloat16 g_vtlo[B_ * H_ * D_ * S_];

// ---------------- PTX helpers ----------------
__device__ __forceinline__ uint32_t smem_to_u32(const void* p) {
    uint32_t a;
    asm("{ .reg .u64 t; cvta.to.shared.u64 t, %1; cvt.u32.u64 %0, t; }"
        : "=r"(a) : "l"(p));
    return a;
}
__device__ __forceinline__ void cp_async16(uint32_t dst, const void* src) {
    asm volatile("cp.async.cg.shared.global [%0], [%1], 16;"
                 :: "r"(dst), "l"(src) : "memory");
}
#define CP_COMMIT() asm volatile("cp.async.commit_group;" ::: "memory")
#define CP_WAIT(n)  asm volatile("cp.async.wait_group %0;" :: "n"(n) : "memory")

__device__ __forceinline__ void ldsm_x4(uint32_t& r0, uint32_t& r1,
                                        uint32_t& r2, uint32_t& r3, uint32_t addr) {
    asm volatile("ldmatrix.sync.aligned.m8n8.x4.shared.b16 {%0,%1,%2,%3}, [%4];"
                 : "=r"(r0), "=r"(r1), "=r"(r2), "=r"(r3) : "r"(addr));
}
// bf16 MMA (attention)
__device__ __forceinline__ void mma16816(float* c, const uint32_t* a, const uint32_t* b) {
    asm volatile("mma.sync.aligned.m16n8k16.row.col.f32.bf16.bf16.f32 "
                 "{%0,%1,%2,%3}, {%4,%5,%6,%7}, {%8,%9}, {%0,%1,%2,%3};"
                 : "+f"(c[0]), "+f"(c[1]), "+f"(c[2]), "+f"(c[3])
                 : "r"(a[0]), "r"(a[1]), "r"(a[2]), "r"(a[3]),
                   "r"(b[0]), "r"(b[1]));
}
// fp16 MMA (GEMMs)
__device__ __forceinline__ void mma16816h(float* c, const uint32_t* a, const uint32_t* b) {
    asm volatile("mma.sync.aligned.m16n8k16.row.col.f32.f16.f16.f32 "
                 "{%0,%1,%2,%3}, {%4,%5,%6,%7}, {%8,%9}, {%0,%1,%2,%3};"
                 : "+f"(c[0]), "+f"(c[1]), "+f"(c[2]), "+f"(c[3])
                 : "r"(a[0]), "r"(a[1]), "r"(a[2]), "r"(a[3]),
                   "r"(b[0]), "r"(b[1]));
}
__device__ __forceinline__ void split32(float v, __nv_bfloat16& h, __nv_bfloat16& l) {
    h = __float2bfloat16(v);
    l = __float2bfloat16(v - __bfloat162float(h));
}
__device__ __forceinline__ void split16(float v, __half& h, __half& l) {
    h = __float2half(v);
    l = __float2half(v - __half2float(h));
}

// ---------------------------------------------------------------------------
// split: fp32 -> (hi, lo) fp16, same layout.
// ---------------------------------------------------------------------------
__global__ void split_kernel(const float* __restrict__ in,
                             __half* __restrict__ hi,
                             __half* __restrict__ lo, int n4)
{
    int i = blockIdx.x * blockDim.x + threadIdx.x;
    if (i >= n4) return;
    float4 v = ((const float4*)in)[i];
    __half h0, h1, h2, h3, l0, l1, l2, l3;
    split16(v.x, h0, l0); split16(v.y, h1, l1);
    split16(v.z, h2, l2); split16(v.w, h3, l3);
    ((__half2*)hi)[2 * i]     = __half2(h0, h1);
    ((__half2*)hi)[2 * i + 1] = __half2(h2, h3);
    ((__half2*)lo)[2 * i]     = __half2(l0, l1);
    ((__half2*)lo)[2 * i + 1] = __half2(l2, l3);
}

// ---------------------------------------------------------------------------
// transpose + truncate: W[K,N] fp32 -> T_h [N,K] fp16
// ---------------------------------------------------------------------------
__global__ void tsplit_kernel(const float* __restrict__ W,
                              __half* __restrict__ Th, int K, int N)
{
    __shared__ float t[32][33];
    int n0 = blockIdx.x * 32, k0 = blockIdx.y * 32;
    int tx = threadIdx.x, ty = threadIdx.y;  // 32 x 8
#pragma unroll
    for (int i = 0; i < 4; i++)
        t[ty + i * 8][tx] = W[(long)(k0 + ty + i * 8) * N + n0 + tx];
    __syncthreads();
#pragma unroll
    for (int i = 0; i < 4; i++) {
        float v = t[tx][ty + i * 8];
        Th[(long)(n0 + ty + i * 8) * K + k0 + tx] = __float2half(v);
    }
}

// ---------------------------------------------------------------------------
// qk_split: qkv fp32 [B,S,3NX] -> Q(scaled)/K bf16 hi/lo in [b,h,s,d]
// ---------------------------------------------------------------------------
__global__ void qk_split(const float* __restrict__ qkv,
                         __nv_bfloat16* __restrict__ Qhi, __nv_bfloat16* __restrict__ Qlo,
                         __nv_bfloat16* __restrict__ Khi, __nv_bfloat16* __restrict__ Klo)
{
    int idx = blockIdx.x * blockDim.x + threadIdx.x;
    if (idx >= B_ * S_ * NX_ / 4) return;
    int c4  = idx & 255;
    long row = idx >> 8;
    int h = c4 >> 4, d4 = c4 & 15;
    int b = (int)(row >> 10), s = (int)(row & 1023);

    float4 q = ((const float4*)(qkv + row * 3072))[c4];
    float4 k = ((const float4*)(qkv + row * 3072 + 1024))[c4];
    q.x *= 0.125f; q.y *= 0.125f; q.z *= 0.125f; q.w *= 0.125f;

    long o = (((long)b * H_ + h) * S_ + s) * D_ + d4 * 4;
    __nv_bfloat16 h0, h1, h2, h3, l0, l1, l2, l3;
    split32(q.x, h0, l0); split32(q.y, h1, l1);
    split32(q.z, h2, l2); split32(q.w, h3, l3);
    *(__nv_bfloat162*)&Qhi[o]     = __nv_bfloat162(h0, h1);
    *(__nv_bfloat162*)&Qhi[o + 2] = __nv_bfloat162(h2, h3);
    *(__nv_bfloat162*)&Qlo[o]     = __nv_bfloat162(l0, l1);
    *(__nv_bfloat162*)&Qlo[o + 2] = __nv_bfloat162(l2, l3);
    split32(k.x, h0, l0); split32(k.y, h1, l1);
    split32(k.z, h2, l2); split32(k.w, h3, l3);
    *(__nv_bfloat162*)&Khi[o]     = __nv_bfloat162(h0, h1);
    *(__nv_bfloat162*)&Khi[o + 2] = __nv_bfloat162(h2, h3);
    *(__nv_bfloat162*)&Klo[o]     = __nv_bfloat162(l0, l1);
    *(__nv_bfloat162*)&Klo[o + 2] = __nv_bfloat162(l2, l3);
}

// ---------------------------------------------------------------------------
// vt_split: V from qkv -> VT bf16 hi/lo [b,h,d,s] (transposed)
// ---------------------------------------------------------------------------
__global__ void vt_split(const float* __restrict__ qkv,
                         __nv_bfloat16* __restrict__ VThi,
                         __nv_bfloat16* __restrict__ VTlo)
{
    __shared__ float t[32][33];
    int bh = blockIdx.z;
    int b = bh >> 4, h = bh & 15;
    int s0 = blockIdx.x * 32, d0 = blockIdx.y * 32;
    int tx = threadIdx.x, ty = threadIdx.y;
    long base = (long)b * S_ * 3072 + 2048 + h * 64;
#pragma unroll
    for (int i = 0; i < 4; i++)
        t[ty + i * 8][tx] = qkv[base + (long)(s0 + ty + i * 8) * 3072 + d0 + tx];
    __syncthreads();
#pragma unroll
    for (int i = 0; i < 4; i++) {
        float v = t[tx][ty + i * 8];
        __nv_bfloat16 hh, ll;
        split32(v, hh, ll);
        long o = ((long)bh * D_ + d0 + ty + i * 8) * S_ + s0 + tx;
        VThi[o] = hh;
        VTlo[o] = ll;
    }
}

// ---------------------------------------------------------------------------
// fp16 2-product GEMM on mma.sync:
//   C[M,N] = (Ahi+Alo)[M,K] x (Bh[N,K])^T + bias[N]
// 128x128x32 tiles, 8 warps (2Mx4N), 3-stage cp.async, 2 CTAs/SM.
// ---------------------------------------------------------------------------
#define ROWB    80
#define TILE_B  (128 * ROWB)             // 10240 B
#define STAGE_B (3 * TILE_B)             // Ahi Alo Bh = 30720 B
#define NSTAGE  3
#define GEMM_SMEM_DYN (NSTAGE * STAGE_B) // 92160 B

__global__ void __launch_bounds__(256, 2) gemm_mma(
    const __half* __restrict__ Ahi, const __half* __restrict__ Alo,
    const __half* __restrict__ Bh,
    const float* __restrict__ bias, float* __restrict__ C,
    int M, int N, int K)
{
    extern __shared__ __align__(128) char smem[];
    const uint32_t sbase = smem_to_u32(smem);

    const int tid  = threadIdx.x;
    const int lane = tid & 31;
    const int wid  = tid >> 5;
    const int wm   = wid & 1;
    const int wn   = wid >> 1;
    const int bm   = blockIdx.y * 128;
    const int bn   = blockIdx.x * 128;

    float acc[4][4][4];
#pragma unroll
    for (int mi = 0; mi < 4; mi++)
#pragma unroll
        for (int ni = 0; ni < 4; ni++)
#pragma unroll
            for (int r = 0; r < 4; r++) acc[mi][ni][r] = 0.f;

    const int row = tid & 127;
    const int ch  = tid >> 7;

    const __half* gA[2] = { Ahi + (long)bm * K, Alo + (long)bm * K };
    const __half* gB = Bh + (long)bn * K;

    const int NS = K / 32;

    auto load_stage = [&](int s) {
        const int k0 = s * 32;
        const uint32_t buf = sbase + (s % NSTAGE) * STAGE_B;
#pragma unroll
        for (int j = 0; j < 2; j++) {
            int c = ch + 2 * j;
#pragma unroll
            for (int t = 0; t < 2; t++)
                cp_async16(buf + t * TILE_B + row * ROWB + c * 16,
                           gA[t] + (long)row * K + k0 + c * 8);
            cp_async16(buf + 2 * TILE_B + row * ROWB + c * 16,
                       gB + (long)row * K + k0 + c * 8);
        }
    };

    load_stage(0);
    CP_COMMIT();
    load_stage(1);
    CP_COMMIT();

    const int arow  = wm * 64 + (lane & 15);
    const int asel  = (lane >> 4) << 3;
    const int brow  = wn * 32 + (lane & 7) + ((lane >> 4) << 3);
    const int bsel  = ((lane >> 3) & 1) << 3;

    for (int s = 0; s < NS; s++) {
        if (s + 2 < NS) {
            load_stage(s + 2);
            CP_COMMIT();
            CP_WAIT(2);
        } else {
            CP_WAIT(0);
        }
        __syncthreads();

        const uint32_t buf = sbase + (s % NSTAGE) * STAGE_B;
#pragma unroll
        for (int ks = 0; ks < 2; ks++) {
            uint32_t a[4][4];
            uint32_t b[4][2];
            const int acol = ks * 16 + asel;
            const int bcol = ks * 16 + bsel;
#pragma unroll
            for (int nj = 0; nj < 2; nj++)
                ldsm_x4(b[nj * 2][0], b[nj * 2][1],
                        b[nj * 2 + 1][0], b[nj * 2 + 1][1],
                        buf + 2 * TILE_B + (brow + nj * 16) * ROWB + bcol * 2);

#pragma unroll
            for (int mi = 0; mi < 4; mi++)
                ldsm_x4(a[mi][0], a[mi][1], a[mi][2], a[mi][3],
                        buf + 0 * TILE_B + (arow + mi * 16) * ROWB + acol * 2);
#pragma unroll
            for (int mi = 0; mi < 4; mi++)
#pragma unroll
                for (int ni = 0; ni < 4; ni++)
                    mma16816h(acc[mi][ni], a[mi], b[ni]);

#pragma unroll
            for (int mi = 0; mi < 4; mi++)
                ldsm_x4(a[mi][0], a[mi][1], a[mi][2], a[mi][3],
                        buf + 1 * TILE_B + (arow + mi * 16) * ROWB + acol * 2);
#pragma unroll
            for (int mi = 0; mi < 4; mi++)
#pragma unroll
                for (int ni = 0; ni < 4; ni++)
                    mma16816h(acc[mi][ni], a[mi], b[ni]);
        }
        __syncthreads();
    }

    const int g  = lane >> 2;
    const int t4 = lane & 3;
#pragma unroll
    for (int mi = 0; mi < 4; mi++) {
#pragma unroll
        for (int ni = 0; ni < 4; ni++) {
            const int col = bn + wn * 32 + ni * 8 + t4 * 2;
            const long r0 = bm + wm * 64 + mi * 16 + g;
            float2 bb = *(const float2*)&bias[col];
            float2 o0 = { acc[mi][ni][0] + bb.x, acc[mi][ni][1] + bb.y };
            float2 o1 = { acc[mi][ni][2] + bb.x, acc[mi][ni][3] + bb.y };
            *(float2*)&C[r0 * N + col] = o0;
            *(float2*)&C[(r0 + 8) * N + col] = o1;
        }
    }
}

// ---------------------------------------------------------------------------
// Causal flash-attention, bf16 3-product HMMA, pre-split operands (unchanged)
// ---------------------------------------------------------------------------
#define ATS 72
#define SST 68

#define Q_HI   0
#define Q_LO   (64 * ATS)
#define K_HI   (2 * 64 * ATS)
#define K_LO   (3 * 64 * ATS)
#define VT_HI  (4 * 64 * ATS)
#define VT_LO  (5 * 64 * ATS)
#define P_HI   (6 * 64 * ATS)
#define P_LO   (7 * 64 * ATS)
#define S_OFF  (8 * 64 * ATS)
#define ATTN2_SMEM (8 * 64 * ATS * 2 + 64 * SST * 4 + 2 * 64 * 4)

__global__ void __launch_bounds__(256, 2) attn_mma(
    const __nv_bfloat16* __restrict__ Qhi, const __nv_bfloat16* __restrict__ Qlo,
    const __nv_bfloat16* __restrict__ Khi, const __nv_bfloat16* __restrict__ Klo,
    const __nv_bfloat16* __restrict__ VThi, const __nv_bfloat16* __restrict__ VTlo,
    float* __restrict__ out)
{
    extern __shared__ __align__(128) char asmem[];
    __nv_bfloat16* bfs = (__nv_bfloat16*)asmem;
    float* Ss      = (float*)(asmem + S_OFF * 2);
    float* alpha_s = Ss + 64 * SST;
    float* linv_s  = alpha_s + 64;
    const uint32_t sb = smem_to_u32(asmem);

    const int tid  = threadIdx.x;
    const int lane = tid & 31;
    const int wid  = tid >> 5;
    const int wm   = wid & 3;
    const int wn   = wid >> 2;
    const int qt   = blockIdx.x;
    const int h    = blockIdx.y;
    const int b    = blockIdx.z;
    const int q0   = qt * 64;
    const int tx   = tid & 15;
    const int ty   = tid >> 4;

    const long bh = (long)b * H_ + h;

    {
        const __nv_bfloat16* qs[2] = { Qhi + (bh * S_ + q0) * D_,
                                       Qlo + (bh * S_ + q0) * D_ };
#pragma unroll
        for (int j = 0; j < 4; j++) {
            int lin = tid + j * 256;
            int t = lin >> 9;
            int r = (lin >> 3) & 63, c = lin & 7;
            cp_async16(sb + (t ? Q_LO : Q_HI) * 2 + r * (ATS * 2) + c * 16,
                       qs[t] + (long)r * D_ + c * 8);
        }
    }

    float m[4], l[4];
    float oacc[4][4];
#pragma unroll
    for (int i = 0; i < 4; i++) {
        m[i] = -1e30f; l[i] = 0.f;
#pragma unroll
        for (int j = 0; j < 4; j++) oacc[i][j] = 0.f;
    }

    const int arow = wm * 16 + (lane & 15);
    const int asel = (lane >> 4) << 3;
    const int brow = wn * 32 + (lane & 7) + ((lane >> 4) << 3);
    const int bsel = ((lane >> 3) & 1) << 3;
    const int g    = lane >> 2;
    const int t4   = lane & 3;

    for (int kt = 0; kt <= qt; kt++) {
        __syncthreads();

        {
            const __nv_bfloat16* srcs[4] = {
                Khi + (bh * S_ + kt * 64) * D_, Klo + (bh * S_ + kt * 64) * D_,
                VThi + bh * D_ * S_ + kt * 64,  VTlo + bh * D_ * S_ + kt * 64 };
            const long rstr[4]  = { D_, D_, S_, S_ };
            const uint32_t dof[4] = { K_HI, K_LO, VT_HI, VT_LO };
#pragma unroll
            for (int j = 0; j < 8; j++) {
                int t = j >> 1;
                int lin = tid + (j & 1) * 256;
                int r = lin >> 3, c = lin & 7;
                cp_async16(sb + dof[t] * 2 + r * (ATS * 2) + c * 16,
                           srcs[t] + (long)r * rstr[t] + c * 8);
            }
        }
        CP_COMMIT();
        CP_WAIT(0);
        __syncthreads();

        float sacc[4][4];
#pragma unroll
        for (int ni = 0; ni < 4; ni++)
#pragma unroll
            for (int r = 0; r < 4; r++) sacc[ni][r] = 0.f;

#pragma unroll
        for (int ks = 0; ks < 4; ks++) {
            const int acol = ks * 16 + asel;
            const int bcol = ks * 16 + bsel;
            uint32_t ah[4], al[4], bh4[4][2], bl4[4][2];
            ldsm_x4(ah[0], ah[1], ah[2], ah[3],
                    sb + (Q_HI + arow * ATS + acol) * 2);
            ldsm_x4(al[0], al[1], al[2], al[3],
                    sb + (Q_LO + arow * ATS + acol) * 2);
#pragma unroll
            for (int nj = 0; nj < 2; nj++) {
                ldsm_x4(bh4[nj * 2][0], bh4[nj * 2][1], bh4[nj * 2 + 1][0], bh4[nj * 2 + 1][1],
                        sb + (K_HI + (brow + nj * 16) * ATS + bcol) * 2);
                ldsm_x4(bl4[nj * 2][0], bl4[nj * 2][1], bl4[nj * 2 + 1][0], bl4[nj * 2 + 1][1],
                        sb + (K_LO + (brow + nj * 16) * ATS + bcol) * 2);
            }
#pragma unroll
            for (int ni = 0; ni < 4; ni++) {
                mma16816(sacc[ni], ah, bh4[ni]);
                mma16816(sacc[ni], ah, bl4[ni]);
                mma16816(sacc[ni], al, bh4[ni]);
            }
        }
#pragma unroll
        for (int ni = 0; ni < 4; ni++) {
            const int col = wn * 32 + ni * 8 + t4 * 2;
            *(float2*)&Ss[(wm * 16 + g) * SST + col]     = make_float2(sacc[ni][0], sacc[ni][1]);
            *(float2*)&Ss[(wm * 16 + g + 8) * SST + col] = make_float2(sacc[ni][2], sacc[ni][3]);
        }
        __syncthreads();

        float s[4][4];
#pragma unroll
        for (int i = 0; i < 4; i++)
#pragma unroll
            for (int j = 0; j < 4; j++)
                s[i][j] = Ss[(ty * 4 + i) * SST + tx * 4 + j];

        if (kt == qt) {
#pragma unroll
            for (int i = 0; i < 4; i++)
#pragma unroll
                for (int j = 0; j < 4; j++)
                    if (tx * 4 + j > ty * 4 + i) s[i][j] = -1e9f;
        }

#pragma unroll
        for (int i = 0; i < 4; i++) {
            float mx = fmaxf(fmaxf(s[i][0], s[i][1]), fmaxf(s[i][2], s[i][3]));
#pragma unroll
            for (int off = 8; off > 0; off >>= 1)
                mx = fmaxf(mx, __shfl_xor_sync(0xffffffffu, mx, off));
            float mnew = fmaxf(m[i], mx);
            float alpha = __expf(m[i] - mnew);
            m[i] = mnew;
            float rs = 0.f;
#pragma unroll
            for (int j = 0; j < 4; j++) {
                s[i][j] = __expf(s[i][j] - mnew);
                rs += s[i][j];
            }
#pragma unroll
            for (int off = 8; off > 0; off >>= 1)
                rs += __shfl_xor_sync(0xffffffffu, rs, off);
            l[i] = l[i] * alpha + rs;
            if (tx == 0) alpha_s[ty * 4 + i] = alpha;
            const int pr = (ty * 4 + i) * ATS + tx * 4;
#pragma unroll
            for (int j = 0; j < 4; j += 2) {
                __nv_bfloat16 h0, l0, h1, l1;
                split32(s[i][j], h0, l0);
                split32(s[i][j + 1], h1, l1);
                *(__nv_bfloat162*)&bfs[P_HI + pr + j] = __nv_bfloat162(h0, h1);
                *(__nv_bfloat162*)&bfs[P_LO + pr + j] = __nv_bfloat162(l0, l1);
            }
        }
        __syncthreads();

        const float al0 = alpha_s[wm * 16 + g];
        const float al1 = alpha_s[wm * 16 + g + 8];
#pragma unroll
        for (int ni = 0; ni < 4; ni++) {
            oacc[ni][0] *= al0; oacc[ni][1] *= al0;
            oacc[ni][2] *= al1; oacc[ni][3] *= al1;
        }
#pragma unroll
        for (int ks = 0; ks < 4; ks++) {
            const int acol = ks * 16 + asel;
            const int bcol = ks * 16 + bsel;
            uint32_t ah[4], al[4], bh4[4][2], bl4[4][2];
            ldsm_x4(ah[0], ah[1], ah[2], ah[3],
                    sb + (P_HI + arow * ATS + acol) * 2);
            ldsm_x4(al[0], al[1], al[2], al[3],
                    sb + (P_LO + arow * ATS + acol) * 2);
#pragma unroll
            for (int nj = 0; nj < 2; nj++) {
                ldsm_x4(bh4[nj * 2][0], bh4[nj * 2][1], bh4[nj * 2 + 1][0], bh4[nj * 2 + 1][1],
                        sb + (VT_HI + (brow + nj * 16) * ATS + bcol) * 2);
                ldsm_x4(bl4[nj * 2][0], bl4[nj * 2][1], bl4[nj * 2 + 1][0], bl4[nj * 2 + 1][1],
                        sb + (VT_LO + (brow + nj * 16) * ATS + bcol) * 2);
            }
#pragma unroll
            for (int ni = 0; ni < 4; ni++) {
                mma16816(oacc[ni], ah, bh4[ni]);
                mma16816(oacc[ni], ah, bl4[ni]);
                mma16816(oacc[ni], al, bh4[ni]);
            }
        }
    }

#pragma unroll
    for (int i = 0; i < 4; i++)
        if (tx == 0) linv_s[ty * 4 + i] = 1.f / l[i];
    __syncthreads();

    const float li0 = linv_s[wm * 16 + g];
    const float li1 = linv_s[wm * 16 + g + 8];
#pragma unroll
    for (int ni = 0; ni < 4; ni++) {
        const int col = h * D_ + wn * 32 + ni * 8 + t4 * 2;
        const long r0 = (long)b * S_ + q0 + wm * 16 + g;
        *(float2*)&out[r0 * NX_ + col] =
            make_float2(oacc[ni][0] * li0, oacc[ni][1] * li0);
        *(float2*)&out[(r0 + 8) * NX_ + col] =
            make_float2(oacc[ni][2] * li1, oacc[ni][3] * li1);
    }
}

// ---------------------------------------------------------------------------
extern "C" void kernel_launch(void* const* d_in, const int* in_sizes, int n_in,
                              void* d_out, int out_size)
{
    const float* x      = (const float*)d_in[0];
    const float* w_attn = (const float*)d_in[1];
    const float* b_attn = (const float*)d_in[2];
    const float* w_proj = (const float*)d_in[3];
    const float* b_proj = (const float*)d_in[4];
    float* out = (float*)d_out;

    float *qkv, *attn;
    __half *xhi, *xlo, *ahi, *alo, *wqh, *wph;
    __nv_bfloat16 *qhi, *qlo, *khi, *klo, *vthi, *vtlo;
    cudaGetSymbolAddress((void**)&qkv, g_qkv);
    cudaGetSymbolAddress((void**)&attn, g_attn);
    cudaGetSymbolAddress((void**)&xhi, g_xhi);
    cudaGetSymbolAddress((void**)&xlo, g_xlo);
    cudaGetSymbolAddress((void**)&ahi, g_ahi);
    cudaGetSymbolAddress((void**)&alo, g_alo);
    cudaGetSymbolAddress((void**)&wqh, g_wqkv_h);
    cudaGetSymbolAddress((void**)&wph, g_wproj_h);
    cudaGetSymbolAddress((void**)&qhi, g_qhi);
    cudaGetSymbolAddress((void**)&qlo, g_qlo);
    cudaGetSymbolAddress((void**)&khi, g_khi);
    cudaGetSymbolAddress((void**)&klo, g_klo);
    cudaGetSymbolAddress((void**)&vthi, g_vthi);
    cudaGetSymbolAddress((void**)&vtlo, g_vtlo);

    cudaFuncSetAttribute(attn_mma,
                         cudaFuncAttributeMaxDynamicSharedMemorySize,
                         ATTN2_SMEM);
    cudaFuncSetAttribute(gemm_mma,
                         cudaFuncAttributeMaxDynamicSharedMemorySize,
                         GEMM_SMEM_DYN);

    const int M = B_ * S_;  // 8192

    // split x (fp16 hi/lo)
    {
        int n4 = M * NX_ / 4;
        split_kernel<<<(n4 + 255) / 256, 256>>>(x, xhi, xlo, n4);
    }
    // transpose+truncate weights (fp16)
    tsplit_kernel<<<dim3(3 * NX_ / 32, NX_ / 32), dim3(32, 8)>>>(w_attn, wqh, NX_, 3 * NX_);
    tsplit_kernel<<<dim3(NX_ / 32, NX_ / 32), dim3(32, 8)>>>(w_proj, wph, NX_, NX_);

    // QKV GEMM (fp16 2-product)
    gemm_mma<<<dim3(3 * NX_ / 128, M / 128), 256, GEMM_SMEM_DYN>>>(
        xhi, xlo, wqh, b_attn, qkv, M, 3 * NX_, NX_);

    // pre-split attention operands (bf16)
    qk_split<<<(M * NX_ / 4 + 255) / 256, 256>>>(qkv, qhi, qlo, khi, klo);
    vt_split<<<dim3(S_ / 32, D_ / 32, B_ * H_), dim3(32, 8)>>>(qkv, vthi, vtlo);

    // attention (bf16 3-product HMMA)
    attn_mma<<<dim3(S_ / 64, H_, B_), 256, ATTN2_SMEM>>>(
        qhi, qlo, khi, klo, vthi, vtlo, attn);

    // split attention output (fp16 hi/lo)
    {
        int n4 = M * NX_ / 4;
        split_kernel<<<(n4 + 255) / 256, 256>>>(attn, ahi, alo, n4);
    }
    // projection GEMM (fp16 2-product)
    gemm_mma<<<dim3(NX_ / 128, M / 128), 256, GEMM_SMEM_DYN>>>(
        ahi, alo, wph, b_proj, out, M, NX_, NX_);
}

// round 9
// speedup vs baseline: 2.5897x; 1.0316x over previous
#include <cuda_runtime.h>
#include <cuda_bf16.h>
#include <cuda_fp16.h>
#include <cstdint>

#define B_  8
#define S_  1024
#define NX_ 1024
#define H_  16
#define D_  64

// ---------------- scratch (__device__ globals; no allocation) ----------------
__device__ __half g_xhi[B_ * S_ * NX_];
__device__ __half g_xlo[B_ * S_ * NX_];
__device__ __half g_ahi[B_ * S_ * NX_];              // attention out, fp16 hi
__device__ __half g_alo[B_ * S_ * NX_];              // attention out, fp16 lo
__device__ __half g_wqkv_h[3 * NX_ * NX_];           // [N=3072, K=1024] fp16 trunc
__device__ __half g_wproj_h[NX_ * NX_];              // [N=1024, K=1024]
// attention operands, written by QKV GEMM epilogue: bf16 hi/lo, [b,h,s,d]
__device__ __nv_bfloat16 g_qhi[B_ * H_ * S_ * D_];   // pre-scaled by 0.125
__device__ __nv_bfloat16 g_qlo[B_ * H_ * S_ * D_];
__device__ __nv_bfloat16 g_khi[B_ * H_ * S_ * D_];
__device__ __nv_bfloat16 g_klo[B_ * H_ * S_ * D_];
__device__ __nv_bfloat16 g_vhi[B_ * H_ * S_ * D_];
__device__ __nv_bfloat16 g_vlo[B_ * H_ * S_ * D_];

// ---------------- PTX helpers ----------------
__device__ __forceinline__ uint32_t smem_to_u32(const void* p) {
    uint32_t a;
    asm("{ .reg .u64 t; cvta.to.shared.u64 t, %1; cvt.u32.u64 %0, t; }"
        : "=r"(a) : "l"(p));
    return a;
}
__device__ __forceinline__ void cp_async16(uint32_t dst, const void* src) {
    asm volatile("cp.async.cg.shared.global [%0], [%1], 16;"
                 :: "r"(dst), "l"(src) : "memory");
}
#define CP_COMMIT() asm volatile("cp.async.commit_group;" ::: "memory")
#define CP_WAIT(n)  asm volatile("cp.async.wait_group %0;" :: "n"(n) : "memory")

__device__ __forceinline__ void ldsm_x4(uint32_t& r0, uint32_t& r1,
                                        uint32_t& r2, uint32_t& r3, uint32_t addr) {
    asm volatile("ldmatrix.sync.aligned.m8n8.x4.shared.b16 {%0,%1,%2,%3}, [%4];"
                 : "=r"(r0), "=r"(r1), "=r"(r2), "=r"(r3) : "r"(addr));
}
__device__ __forceinline__ void ldsm_x4t(uint32_t& r0, uint32_t& r1,
                                         uint32_t& r2, uint32_t& r3, uint32_t addr) {
    asm volatile("ldmatrix.sync.aligned.m8n8.x4.trans.shared.b16 {%0,%1,%2,%3}, [%4];"
                 : "=r"(r0), "=r"(r1), "=r"(r2), "=r"(r3) : "r"(addr));
}
// bf16 MMA (attention)
__device__ __forceinline__ void mma16816(float* c, const uint32_t* a, const uint32_t* b) {
    asm volatile("mma.sync.aligned.m16n8k16.row.col.f32.bf16.bf16.f32 "
                 "{%0,%1,%2,%3}, {%4,%5,%6,%7}, {%8,%9}, {%0,%1,%2,%3};"
                 : "+f"(c[0]), "+f"(c[1]), "+f"(c[2]), "+f"(c[3])
                 : "r"(a[0]), "r"(a[1]), "r"(a[2]), "r"(a[3]),
                   "r"(b[0]), "r"(b[1]));
}
// fp16 MMA (GEMMs)
__device__ __forceinline__ void mma16816h(float* c, const uint32_t* a, const uint32_t* b) {
    asm volatile("mma.sync.aligned.m16n8k16.row.col.f32.f16.f16.f32 "
                 "{%0,%1,%2,%3}, {%4,%5,%6,%7}, {%8,%9}, {%0,%1,%2,%3};"
                 : "+f"(c[0]), "+f"(c[1]), "+f"(c[2]), "+f"(c[3])
                 : "r"(a[0]), "r"(a[1]), "r"(a[2]), "r"(a[3]),
                   "r"(b[0]), "r"(b[1]));
}
__device__ __forceinline__ void split32(float v, __nv_bfloat16& h, __nv_bfloat16& l) {
    h = __float2bfloat16(v);
    l = __float2bfloat16(v - __bfloat162float(h));
}
__device__ __forceinline__ void split16(float v, __half& h, __half& l) {
    h = __float2half(v);
    l = __float2half(v - __half2float(h));
}

// ---------------------------------------------------------------------------
// split: fp32 -> (hi, lo) fp16, same layout (input x only).
// ---------------------------------------------------------------------------
__global__ void split_kernel(const float* __restrict__ in,
                             __half* __restrict__ hi,
                             __half* __restrict__ lo, int n4)
{
    int i = blockIdx.x * blockDim.x + threadIdx.x;
    if (i >= n4) return;
    float4 v = ((const float4*)in)[i];
    __half h0, h1, h2, h3, l0, l1, l2, l3;
    split16(v.x, h0, l0); split16(v.y, h1, l1);
    split16(v.z, h2, l2); split16(v.w, h3, l3);
    ((__half2*)hi)[2 * i]     = __half2(h0, h1);
    ((__half2*)hi)[2 * i + 1] = __half2(h2, h3);
    ((__half2*)lo)[2 * i]     = __half2(l0, l1);
    ((__half2*)lo)[2 * i + 1] = __half2(l2, l3);
}

// ---------------------------------------------------------------------------
// transpose + truncate: W[K,N] fp32 -> T_h [N,K] fp16
// ---------------------------------------------------------------------------
__global__ void tsplit_kernel(const float* __restrict__ W,
                              __half* __restrict__ Th, int K, int N)
{
    __shared__ float t[32][33];
    int n0 = blockIdx.x * 32, k0 = blockIdx.y * 32;
    int tx = threadIdx.x, ty = threadIdx.y;  // 32 x 8
#pragma unroll
    for (int i = 0; i < 4; i++)
        t[ty + i * 8][tx] = W[(long)(k0 + ty + i * 8) * N + n0 + tx];
    __syncthreads();
#pragma unroll
    for (int i = 0; i < 4; i++) {
        float v = t[tx][ty + i * 8];
        Th[(long)(n0 + ty + i * 8) * K + k0 + tx] = __float2half(v);
    }
}

// ---------------------------------------------------------------------------
// Shared GEMM mainloop (fp16 2-product, 128x128x32, 8 warps 2Mx4N, 3-stage).
// Produces acc[4][4][4]; epilogues differ per kernel.
// ---------------------------------------------------------------------------
#define ROWB    80
#define TILE_B  (128 * ROWB)
#define STAGE_B (3 * TILE_B)
#define NSTAGE  3
#define GEMM_SMEM_DYN (NSTAGE * STAGE_B)

#define GEMM_MAINLOOP(Ahi, Alo, Bh, K)                                          \
    extern __shared__ __align__(128) char smem[];                               \
    const uint32_t sbase = smem_to_u32(smem);                                   \
    const int tid  = threadIdx.x;                                               \
    const int lane = tid & 31;                                                  \
    const int wid  = tid >> 5;                                                  \
    const int wm   = wid & 1;                                                   \
    const int wn   = wid >> 1;                                                  \
    const int bm   = blockIdx.y * 128;                                          \
    const int bn   = blockIdx.x * 128;                                          \
    float acc[4][4][4];                                                         \
    _Pragma("unroll")                                                           \
    for (int mi = 0; mi < 4; mi++)                                              \
        _Pragma("unroll")                                                       \
        for (int ni = 0; ni < 4; ni++)                                          \
            _Pragma("unroll")                                                   \
            for (int r = 0; r < 4; r++) acc[mi][ni][r] = 0.f;                   \
    const int row = tid & 127;                                                  \
    const int ch  = tid >> 7;                                                   \
    const __half* gA[2] = { Ahi + (long)bm * (K), Alo + (long)bm * (K) };       \
    const __half* gB = Bh + (long)bn * (K);                                     \
    const int NS = (K) / 32;                                                    \
    auto load_stage = [&](int s) {                                              \
        const int k0 = s * 32;                                                  \
        const uint32_t buf = sbase + (s % NSTAGE) * STAGE_B;                    \
        _Pragma("unroll")                                                       \
        for (int j = 0; j < 2; j++) {                                           \
            int c = ch + 2 * j;                                                 \
            _Pragma("unroll")                                                   \
            for (int t = 0; t < 2; t++)                                         \
                cp_async16(buf + t * TILE_B + row * ROWB + c * 16,              \
                           gA[t] + (long)row * (K) + k0 + c * 8);               \
            cp_async16(buf + 2 * TILE_B + row * ROWB + c * 16,                  \
                       gB + (long)row * (K) + k0 + c * 8);                      \
        }                                                                       \
    };                                                                          \
    load_stage(0);                                                              \
    CP_COMMIT();                                                                \
    load_stage(1);                                                              \
    CP_COMMIT();                                                                \
    const int arow  = wm * 64 + (lane & 15);                                    \
    const int asel  = (lane >> 4) << 3;                                         \
    const int brow  = wn * 32 + (lane & 7) + ((lane >> 4) << 3);                \
    const int bsel  = ((lane >> 3) & 1) << 3;                                   \
    for (int s = 0; s < NS; s++) {                                              \
        if (s + 2 < NS) {                                                       \
            load_stage(s + 2);                                                  \
            CP_COMMIT();                                                        \
            CP_WAIT(2);                                                         \
        } else {                                                                \
            CP_WAIT(0);                                                         \
        }                                                                       \
        __syncthreads();                                                        \
        const uint32_t buf = sbase + (s % NSTAGE) * STAGE_B;                    \
        _Pragma("unroll")                                                       \
        for (int ks = 0; ks < 2; ks++) {                                        \
            uint32_t a[4][4];                                                   \
            uint32_t b[4][2];                                                   \
            const int acol = ks * 16 + asel;                                    \
            const int bcol = ks * 16 + bsel;                                    \
            _Pragma("unroll")                                                   \
            for (int nj = 0; nj < 2; nj++)                                      \
                ldsm_x4(b[nj * 2][0], b[nj * 2][1],                             \
                        b[nj * 2 + 1][0], b[nj * 2 + 1][1],                     \
                        buf + 2 * TILE_B + (brow + nj * 16) * ROWB + bcol * 2); \
            _Pragma("unroll")                                                   \
            for (int mi = 0; mi < 4; mi++)                                      \
                ldsm_x4(a[mi][0], a[mi][1], a[mi][2], a[mi][3],                 \
                        buf + 0 * TILE_B + (arow + mi * 16) * ROWB + acol * 2); \
            _Pragma("unroll")                                                   \
            for (int mi = 0; mi < 4; mi++)                                      \
                _Pragma("unroll")                                               \
                for (int ni = 0; ni < 4; ni++)                                  \
                    mma16816h(acc[mi][ni], a[mi], b[ni]);                       \
            _Pragma("unroll")                                                   \
            for (int mi = 0; mi < 4; mi++)                                      \
                ldsm_x4(a[mi][0], a[mi][1], a[mi][2], a[mi][3],                 \
                        buf + 1 * TILE_B + (arow + mi * 16) * ROWB + acol * 2); \
            _Pragma("unroll")                                                   \
            for (int mi = 0; mi < 4; mi++)                                      \
                _Pragma("unroll")                                               \
                for (int ni = 0; ni < 4; ni++)                                  \
                    mma16816h(acc[mi][ni], a[mi], b[ni]);                       \
        }                                                                       \
        __syncthreads();                                                        \
    }

// ---------------------------------------------------------------------------
// Projection GEMM: fp32 out + bias (final output)
// ---------------------------------------------------------------------------
__global__ void __launch_bounds__(256, 2) gemm_proj(
    const __half* __restrict__ Ahi, const __half* __restrict__ Alo,
    const __half* __restrict__ Bh,
    const float* __restrict__ bias, float* __restrict__ C, int N, int K)
{
    GEMM_MAINLOOP(Ahi, Alo, Bh, K)

    const int g  = lane >> 2;
    const int t4 = lane & 3;
#pragma unroll
    for (int mi = 0; mi < 4; mi++) {
#pragma unroll
        for (int ni = 0; ni < 4; ni++) {
            const int col = bn + wn * 32 + ni * 8 + t4 * 2;
            const long r0 = bm + wm * 64 + mi * 16 + g;
            float2 bb = *(const float2*)&bias[col];
            float2 o0 = { acc[mi][ni][0] + bb.x, acc[mi][ni][1] + bb.y };
            float2 o1 = { acc[mi][ni][2] + bb.x, acc[mi][ni][3] + bb.y };
            *(float2*)&C[r0 * N + col] = o0;
            *(float2*)&C[(r0 + 8) * N + col] = o1;
        }
    }
}

// ---------------------------------------------------------------------------
// QKV GEMM: epilogue writes Q(scaled)/K/V bf16 hi/lo directly to [b,h,s,d].
// Region (Q/K/V) is CTA-uniform: N-tile (128) never straddles 1024 boundaries.
// ---------------------------------------------------------------------------
__global__ void __launch_bounds__(256, 2) gemm_qkv(
    const __half* __restrict__ Ahi, const __half* __restrict__ Alo,
    const __half* __restrict__ Bh, const float* __restrict__ bias,
    __nv_bfloat16* __restrict__ Qhi, __nv_bfloat16* __restrict__ Qlo,
    __nv_bfloat16* __restrict__ Khi, __nv_bfloat16* __restrict__ Klo,
    __nv_bfloat16* __restrict__ Vhi, __nv_bfloat16* __restrict__ Vlo,
    int K)
{
    GEMM_MAINLOOP(Ahi, Alo, Bh, K)

    const int g  = lane >> 2;
    const int t4 = lane & 3;
    const int region = bn >> 10;            // 0=Q 1=K 2=V
    __nv_bfloat16 *Dhi, *Dlo;
    float scale = 1.f;
    if (region == 0) { Dhi = Qhi; Dlo = Qlo; scale = 0.125f; }
    else if (region == 1) { Dhi = Khi; Dlo = Klo; }
    else { Dhi = Vhi; Dlo = Vlo; }

#pragma unroll
    for (int mi = 0; mi < 4; mi++) {
#pragma unroll
        for (int ni = 0; ni < 4; ni++) {
            const int colg = bn + wn * 32 + ni * 8 + t4 * 2;   // global col
            const int c    = colg & 1023;
            const int h    = c >> 6, d = c & 63;
            const long r0  = bm + wm * 64 + mi * 16 + g;       // = b*S + s
            const int b    = (int)(r0 >> 10);
            const int s    = (int)(r0 & 1023);
            float2 bb = *(const float2*)&bias[colg];
            long o = (((long)b * H_ + h) * S_ + s) * D_ + d;
            __nv_bfloat16 h0, l0, h1, l1;
            split32((acc[mi][ni][0] + bb.x) * scale, h0, l0);
            split32((acc[mi][ni][1] + bb.y) * scale, h1, l1);
            *(__nv_bfloat162*)&Dhi[o] = __nv_bfloat162(h0, h1);
            *(__nv_bfloat162*)&Dlo[o] = __nv_bfloat162(l0, l1);
            split32((acc[mi][ni][2] + bb.x) * scale, h0, l0);
            split32((acc[mi][ni][3] + bb.y) * scale, h1, l1);
            *(__nv_bfloat162*)&Dhi[o + 8 * D_] = __nv_bfloat162(h0, h1);
            *(__nv_bfloat162*)&Dlo[o + 8 * D_] = __nv_bfloat162(l0, l1);
        }
    }
}

// ---------------------------------------------------------------------------
// Causal flash-attention: bf16 3-product HMMA; V in [s][d], PV uses trans-ldsm.
// Epilogue writes fp16 hi/lo directly (proj GEMM input).
// ---------------------------------------------------------------------------
#define ATS 72
#define SST 68

#define Q_HI   0
#define Q_LO   (64 * ATS)
#define K_HI   (2 * 64 * ATS)
#define K_LO   (3 * 64 * ATS)
#define V_HI   (4 * 64 * ATS)
#define V_LO   (5 * 64 * ATS)
#define P_HI   (6 * 64 * ATS)
#define P_LO   (7 * 64 * ATS)
#define S_OFF  (8 * 64 * ATS)
#define ATTN2_SMEM (8 * 64 * ATS * 2 + 64 * SST * 4 + 2 * 64 * 4)

__global__ void __launch_bounds__(256, 2) attn_mma(
    const __nv_bfloat16* __restrict__ Qhi, const __nv_bfloat16* __restrict__ Qlo,
    const __nv_bfloat16* __restrict__ Khi, const __nv_bfloat16* __restrict__ Klo,
    const __nv_bfloat16* __restrict__ Vhi, const __nv_bfloat16* __restrict__ Vlo,
    __half* __restrict__ Ohi, __half* __restrict__ Olo)
{
    extern __shared__ __align__(128) char asmem[];
    __nv_bfloat16* bfs = (__nv_bfloat16*)asmem;
    float* Ss      = (float*)(asmem + S_OFF * 2);
    float* alpha_s = Ss + 64 * SST;
    float* linv_s  = alpha_s + 64;
    const uint32_t sb = smem_to_u32(asmem);

    const int tid  = threadIdx.x;
    const int lane = tid & 31;
    const int wid  = tid >> 5;
    const int wm   = wid & 3;
    const int wn   = wid >> 2;
    const int qt   = blockIdx.x;
    const int h    = blockIdx.y;
    const int b    = blockIdx.z;
    const int q0   = qt * 64;
    const int tx   = tid & 15;
    const int ty   = tid >> 4;

    const long bh = (long)b * H_ + h;

    {
        const __nv_bfloat16* qs[2] = { Qhi + (bh * S_ + q0) * D_,
                                       Qlo + (bh * S_ + q0) * D_ };
#pragma unroll
        for (int j = 0; j < 4; j++) {
            int lin = tid + j * 256;
            int t = lin >> 9;
            int r = (lin >> 3) & 63, c = lin & 7;
            cp_async16(sb + (t ? Q_LO : Q_HI) * 2 + r * (ATS * 2) + c * 16,
                       qs[t] + (long)r * D_ + c * 8);
        }
    }

    float m[4], l[4];
    float oacc[4][4];
#pragma unroll
    for (int i = 0; i < 4; i++) {
        m[i] = -1e30f; l[i] = 0.f;
#pragma unroll
        for (int j = 0; j < 4; j++) oacc[i][j] = 0.f;
    }

    const int arow = wm * 16 + (lane & 15);
    const int asel = (lane >> 4) << 3;
    const int brow = wn * 32 + (lane & 7) + ((lane >> 4) << 3);
    const int bsel = ((lane >> 3) & 1) << 3;
    // trans-ldmatrix addressing for V[k][d] -> B fragments of [d][k]
    const int vrow = ((lane >> 3) & 1) * 8 + (lane & 7);   // k within 16-chunk
    const int vcol = wn * 32 + ((lane >> 4) << 3);         // d base
    const int g    = lane >> 2;
    const int t4   = lane & 3;

    for (int kt = 0; kt <= qt; kt++) {
        __syncthreads();

        {
            const __nv_bfloat16* srcs[4] = {
                Khi + (bh * S_ + kt * 64) * D_, Klo + (bh * S_ + kt * 64) * D_,
                Vhi + (bh * S_ + kt * 64) * D_, Vlo + (bh * S_ + kt * 64) * D_ };
            const uint32_t dof[4] = { K_HI, K_LO, V_HI, V_LO };
#pragma unroll
            for (int j = 0; j < 8; j++) {
                int t = j >> 1;
                int lin = tid + (j & 1) * 256;
                int r = lin >> 3, c = lin & 7;
                cp_async16(sb + dof[t] * 2 + r * (ATS * 2) + c * 16,
                           srcs[t] + (long)r * D_ + c * 8);
            }
        }
        CP_COMMIT();
        CP_WAIT(0);
        __syncthreads();

        float sacc[4][4];
#pragma unroll
        for (int ni = 0; ni < 4; ni++)
#pragma unroll
            for (int r = 0; r < 4; r++) sacc[ni][r] = 0.f;

#pragma unroll
        for (int ks = 0; ks < 4; ks++) {
            const int acol = ks * 16 + asel;
            const int bcol = ks * 16 + bsel;
            uint32_t ah[4], al[4], bh4[4][2], bl4[4][2];
            ldsm_x4(ah[0], ah[1], ah[2], ah[3],
                    sb + (Q_HI + arow * ATS + acol) * 2);
            ldsm_x4(al[0], al[1], al[2], al[3],
                    sb + (Q_LO + arow * ATS + acol) * 2);
#pragma unroll
            for (int nj = 0; nj < 2; nj++) {
                ldsm_x4(bh4[nj * 2][0], bh4[nj * 2][1], bh4[nj * 2 + 1][0], bh4[nj * 2 + 1][1],
                        sb + (K_HI + (brow + nj * 16) * ATS + bcol) * 2);
                ldsm_x4(bl4[nj * 2][0], bl4[nj * 2][1], bl4[nj * 2 + 1][0], bl4[nj * 2 + 1][1],
                        sb + (K_LO + (brow + nj * 16) * ATS + bcol) * 2);
            }
#pragma unroll
            for (int ni = 0; ni < 4; ni++) {
                mma16816(sacc[ni], ah, bh4[ni]);
                mma16816(sacc[ni], ah, bl4[ni]);
                mma16816(sacc[ni], al, bh4[ni]);
            }
        }
#pragma unroll
        for (int ni = 0; ni < 4; ni++) {
            const int col = wn * 32 + ni * 8 + t4 * 2;
            *(float2*)&Ss[(wm * 16 + g) * SST + col]     = make_float2(sacc[ni][0], sacc[ni][1]);
            *(float2*)&Ss[(wm * 16 + g + 8) * SST + col] = make_float2(sacc[ni][2], sacc[ni][3]);
        }
        __syncthreads();

        float s[4][4];
#pragma unroll
        for (int i = 0; i < 4; i++)
#pragma unroll
            for (int j = 0; j < 4; j++)
                s[i][j] = Ss[(ty * 4 + i) * SST + tx * 4 + j];

        if (kt == qt) {
#pragma unroll
            for (int i = 0; i < 4; i++)
#pragma unroll
                for (int j = 0; j < 4; j++)
                    if (tx * 4 + j > ty * 4 + i) s[i][j] = -1e9f;
        }

#pragma unroll
        for (int i = 0; i < 4; i++) {
            float mx = fmaxf(fmaxf(s[i][0], s[i][1]), fmaxf(s[i][2], s[i][3]));
#pragma unroll
            for (int off = 8; off > 0; off >>= 1)
                mx = fmaxf(mx, __shfl_xor_sync(0xffffffffu, mx, off));
            float mnew = fmaxf(m[i], mx);
            float alpha = __expf(m[i] - mnew);
            m[i] = mnew;
            float rs = 0.f;
#pragma unroll
            for (int j = 0; j < 4; j++) {
                s[i][j] = __expf(s[i][j] - mnew);
                rs += s[i][j];
            }
#pragma unroll
            for (int off = 8; off > 0; off >>= 1)
                rs += __shfl_xor_sync(0xffffffffu, rs, off);
            l[i] = l[i] * alpha + rs;
            if (tx == 0) alpha_s[ty * 4 + i] = alpha;
            const int pr = (ty * 4 + i) * ATS + tx * 4;
#pragma unroll
            for (int j = 0; j < 4; j += 2) {
                __nv_bfloat16 h0, l0, h1, l1;
                split32(s[i][j], h0, l0);
                split32(s[i][j + 1], h1, l1);
                *(__nv_bfloat162*)&bfs[P_HI + pr + j] = __nv_bfloat162(h0, h1);
                *(__nv_bfloat162*)&bfs[P_LO + pr + j] = __nv_bfloat162(l0, l1);
            }
        }
        __syncthreads();

        const float al0 = alpha_s[wm * 16 + g];
        const float al1 = alpha_s[wm * 16 + g + 8];
#pragma unroll
        for (int ni = 0; ni < 4; ni++) {
            oacc[ni][0] *= al0; oacc[ni][1] *= al0;
            oacc[ni][2] *= al1; oacc[ni][3] *= al1;
        }
#pragma unroll
        for (int ks = 0; ks < 4; ks++) {
            const int acol = ks * 16 + asel;
            uint32_t ah[4], al[4], bh4[4][2], bl4[4][2];
            ldsm_x4(ah[0], ah[1], ah[2], ah[3],
                    sb + (P_HI + arow * ATS + acol) * 2);
            ldsm_x4(al[0], al[1], al[2], al[3],
                    sb + (P_LO + arow * ATS + acol) * 2);
            // V fragments via trans ldmatrix on [k][d] tiles
#pragma unroll
            for (int nj = 0; nj < 2; nj++) {
                const uint32_t vaddr = (ks * 16 + vrow) * ATS + vcol + nj * 16;
                ldsm_x4t(bh4[nj * 2][0], bh4[nj * 2][1], bh4[nj * 2 + 1][0], bh4[nj * 2 + 1][1],
                         sb + (V_HI + vaddr) * 2);
                ldsm_x4t(bl4[nj * 2][0], bl4[nj * 2][1], bl4[nj * 2 + 1][0], bl4[nj * 2 + 1][1],
                         sb + (V_LO + vaddr) * 2);
            }
#pragma unroll
            for (int ni = 0; ni < 4; ni++) {
                mma16816(oacc[ni], ah, bh4[ni]);
                mma16816(oacc[ni], ah, bl4[ni]);
                mma16816(oacc[ni], al, bh4[ni]);
            }
        }
    }

#pragma unroll
    for (int i = 0; i < 4; i++)
        if (tx == 0) linv_s[ty * 4 + i] = 1.f / l[i];
    __syncthreads();

    const float li0 = linv_s[wm * 16 + g];
    const float li1 = linv_s[wm * 16 + g + 8];
#pragma unroll
    for (int ni = 0; ni < 4; ni++) {
        const int col = h * D_ + wn * 32 + ni * 8 + t4 * 2;
        const long r0 = (long)b * S_ + q0 + wm * 16 + g;
        __half h0, l0, h1, l1;
        split16(oacc[ni][0] * li0, h0, l0);
        split16(oacc[ni][1] * li0, h1, l1);
        *(__half2*)&Ohi[r0 * NX_ + col] = __half2(h0, h1);
        *(__half2*)&Olo[r0 * NX_ + col] = __half2(l0, l1);
        split16(oacc[ni][2] * li1, h0, l0);
        split16(oacc[ni][3] * li1, h1, l1);
        *(__half2*)&Ohi[(r0 + 8) * NX_ + col] = __half2(h0, h1);
        *(__half2*)&Olo[(r0 + 8) * NX_ + col] = __half2(l0, l1);
    }
}

// ---------------------------------------------------------------------------
extern "C" void kernel_launch(void* const* d_in, const int* in_sizes, int n_in,
                              void* d_out, int out_size)
{
    const float* x      = (const float*)d_in[0];
    const float* w_attn = (const float*)d_in[1];
    const float* b_attn = (const float*)d_in[2];
    const float* w_proj = (const float*)d_in[3];
    const float* b_proj = (const float*)d_in[4];
    float* out = (float*)d_out;

    __half *xhi, *xlo, *ahi, *alo, *wqh, *wph;
    __nv_bfloat16 *qhi, *qlo, *khi, *klo, *vhi, *vlo;
    cudaGetSymbolAddress((void**)&xhi, g_xhi);
    cudaGetSymbolAddress((void**)&xlo, g_xlo);
    cudaGetSymbolAddress((void**)&ahi, g_ahi);
    cudaGetSymbolAddress((void**)&alo, g_alo);
    cudaGetSymbolAddress((void**)&wqh, g_wqkv_h);
    cudaGetSymbolAddress((void**)&wph, g_wproj_h);
    cudaGetSymbolAddress((void**)&qhi, g_qhi);
    cudaGetSymbolAddress((void**)&qlo, g_qlo);
    cudaGetSymbolAddress((void**)&khi, g_khi);
    cudaGetSymbolAddress((void**)&klo, g_klo);
    cudaGetSymbolAddress((void**)&vhi, g_vhi);
    cudaGetSymbolAddress((void**)&vlo, g_vlo);

    cudaFuncSetAttribute(attn_mma,
                         cudaFuncAttributeMaxDynamicSharedMemorySize, ATTN2_SMEM);
    cudaFuncSetAttribute(gemm_qkv,
                         cudaFuncAttributeMaxDynamicSharedMemorySize, GEMM_SMEM_DYN);
    cudaFuncSetAttribute(gemm_proj,
                         cudaFuncAttributeMaxDynamicSharedMemorySize, GEMM_SMEM_DYN);

    const int M = B_ * S_;  // 8192

    // split x (fp16 hi/lo)
    {
        int n4 = M * NX_ / 4;
        split_kernel<<<(n4 + 255) / 256, 256>>>(x, xhi, xlo, n4);
    }
    // transpose+truncate weights (fp16)
    tsplit_kernel<<<dim3(3 * NX_ / 32, NX_ / 32), dim3(32, 8)>>>(w_attn, wqh, NX_, 3 * NX_);
    tsplit_kernel<<<dim3(NX_ / 32, NX_ / 32), dim3(32, 8)>>>(w_proj, wph, NX_, NX_);

    // QKV GEMM with fused split epilogue -> q/k/v bf16 hi/lo [b,h,s,d]
    gemm_qkv<<<dim3(3 * NX_ / 128, M / 128), 256, GEMM_SMEM_DYN>>>(
        xhi, xlo, wqh, b_attn, qhi, qlo, khi, klo, vhi, vlo, NX_);

    // attention (bf16 3-product HMMA) -> fp16 hi/lo directly
    attn_mma<<<dim3(S_ / 64, H_, B_), 256, ATTN2_SMEM>>>(
        qhi, qlo, khi, klo, vhi, vlo, ahi, alo);

    // projection GEMM -> final fp32 output
    gemm_proj<<<dim3(NX_ / 128, M / 128), 256, GEMM_SMEM_DYN>>>(
        ahi, alo, wph, b_proj, out, NX_, NX_);
}